// round 1
// baseline (speedup 1.0000x reference)
#include <cuda_runtime.h>
#include <math.h>

#define E_ 768
#define L_ 12
#define H_ 12
#define D_ 64
#define B_ 2
#define T_ 1024
#define V_ 50257
#define M_ (B_*T_)           // 2048 rows

// ---------------- scratch (static device globals; no allocs) ----------------
__device__ float g_x  [M_*E_];
__device__ float g_xln[M_*E_];
__device__ float g_qkv[M_*3*E_];
__device__ float g_q  [B_*H_*T_*D_];
__device__ float g_k  [B_*H_*T_*D_];
__device__ float g_v  [B_*H_*T_*D_];
__device__ float g_y  [M_*E_];
__device__ float g_h4 [M_*4*E_];

// ---------------- embedding ----------------
__global__ void embed_k(const int* __restrict__ idx, const float* __restrict__ wte,
                        const float* __restrict__ wpe, float* __restrict__ x) {
    int i = blockIdx.x * blockDim.x + threadIdx.x;
    if (i >= M_*E_) return;
    int row = i / E_, e = i % E_;
    int t = row & (T_-1);
    x[i] = wte[(size_t)idx[row]*E_ + e] + wpe[t*E_ + e];
}

// ---------------- layernorm (1 block / row) ----------------
__global__ void ln_k(const float* __restrict__ x, const float* __restrict__ g,
                     const float* __restrict__ b, float* __restrict__ o) {
    int row = blockIdx.x;
    int tid = threadIdx.x;
    const float* xr = x + (size_t)row*E_;
    __shared__ float s1[256], s2[256];
    float a = 0.f, q = 0.f;
    for (int e = tid; e < E_; e += 256) { float v = xr[e]; a += v; q += v*v; }
    s1[tid] = a; s2[tid] = q; __syncthreads();
    for (int off = 128; off > 0; off >>= 1) {
        if (tid < off) { s1[tid] += s1[tid+off]; s2[tid] += s2[tid+off]; }
        __syncthreads();
    }
    float mu  = s1[0] * (1.f/E_);
    float var = s2[0] * (1.f/E_) - mu*mu;
    float inv = rsqrtf(var + 1e-5f);
    for (int e = tid; e < E_; e += 256)
        o[(size_t)row*E_ + e] = (xr[e] - mu) * inv * g[e] + b[e];
}

// ---------------- split qkv -> per-head [B,H,T,D] ----------------
__global__ void split_k(const float* __restrict__ qkv, float* __restrict__ q,
                        float* __restrict__ k, float* __restrict__ v) {
    int i = blockIdx.x * blockDim.x + threadIdx.x;
    if (i >= M_*3*E_) return;
    int row = i / (3*E_), col = i % (3*E_);
    int which = col / E_;  int e = col % E_;
    int h = e >> 6, d = e & 63;
    int b = row >> 10, t = row & (T_-1);
    float val = qkv[i];
    float* dst = (which == 0) ? q : (which == 1) ? k : v;
    dst[(((b*H_ + h)*T_) + t)*D_ + d] = val;
}

// ---------------- causal attention: 1 block per (b,h,tq) ----------------
__global__ void attn_k(const float* __restrict__ qh, const float* __restrict__ kh,
                       const float* __restrict__ vh, float* __restrict__ y) {
    int tq = blockIdx.x;
    int bh = blockIdx.y;          // b*H + h
    int tid = threadIdx.x;        // 128 threads
    __shared__ __align__(16) float qs[D_];
    __shared__ float sc[T_];
    __shared__ float red[128];

    const float* qrow = qh + ((size_t)bh*T_ + tq)*D_;
    if (tid < D_) qs[tid] = qrow[tid];
    __syncthreads();

    const float* kbase = kh + (size_t)bh*T_*D_;
    for (int s = tid; s <= tq; s += 128) {
        const float4* kr = (const float4*)(kbase + (size_t)s*D_);
        const float4* q4 = (const float4*)qs;
        float acc = 0.f;
        #pragma unroll
        for (int j = 0; j < 16; j++) {
            float4 kk = kr[j], qq = q4[j];
            acc += kk.x*qq.x + kk.y*qq.y + kk.z*qq.z + kk.w*qq.w;
        }
        sc[s] = acc * 0.125f;     // 1/sqrt(64)
    }
    __syncthreads();

    // max
    float m = -1e30f;
    for (int s = tid; s <= tq; s += 128) m = fmaxf(m, sc[s]);
    red[tid] = m; __syncthreads();
    for (int off = 64; off > 0; off >>= 1) {
        if (tid < off) red[tid] = fmaxf(red[tid], red[tid+off]);
        __syncthreads();
    }
    m = red[0]; __syncthreads();

    // exp + sum
    float sum = 0.f;
    for (int s = tid; s <= tq; s += 128) {
        float e = __expf(sc[s] - m);
        sc[s] = e; sum += e;
    }
    red[tid] = sum; __syncthreads();
    for (int off = 64; off > 0; off >>= 1) {
        if (tid < off) red[tid] += red[tid+off];
        __syncthreads();
    }
    float inv = 1.f / red[0];
    __syncthreads();

    // weighted sum of V: threads split (d, half)
    int d = tid & 63, half = tid >> 6;
    const float* vbase = vh + (size_t)bh*T_*D_;
    float acc = 0.f;
    for (int s = half; s <= tq; s += 2) acc += sc[s] * vbase[(size_t)s*D_ + d];
    red[tid] = acc; __syncthreads();
    if (tid < D_) {
        float o = (red[tid] + red[tid+64]) * inv;
        int b = bh / H_, h = bh % H_;
        y[((size_t)(b*T_ + tq))*E_ + h*D_ + tid] = o;
    }
}

// ---------------- tiled SGEMM 128x128x16, 8x8 per thread ----------------
// EPI: 0 = none, 1 = +bias, 2 = gelu(+bias), 3 = +bias+residual
// BT:  false -> B is [K,N] row-major;  true -> B is [N,K] row-major (B^T)
template<int EPI, bool BT>
__global__ void __launch_bounds__(256, 2)
sgemm_k(const float* __restrict__ A, const float* __restrict__ B,
        const float* __restrict__ bias, const float* __restrict__ res,
        float* __restrict__ C, int M, int N, int K) {
    __shared__ __align__(16) float As[16][128];
    __shared__ __align__(16) float Bs[16][128];

    int tid = threadIdx.x;
    int tx = tid & 15, ty = tid >> 4;
    int n0 = blockIdx.x * 128;
    int m0 = blockIdx.y * 128;

    float acc[8][8];
    #pragma unroll
    for (int i = 0; i < 8; i++)
        #pragma unroll
        for (int j = 0; j < 8; j++) acc[i][j] = 0.f;

    for (int k0 = 0; k0 < K; k0 += 16) {
        // load A tile (128 x 16) transposed into As[k][m]
        #pragma unroll
        for (int rep = 0; rep < 2; rep++) {
            int f = tid + rep*256;            // 0..511 float4s
            int r = f >> 2, c4 = (f & 3) * 4; // row 0..127, kcol 0..12
            const float4 v = *(const float4*)(A + (size_t)(m0 + r)*K + k0 + c4);
            As[c4+0][r] = v.x; As[c4+1][r] = v.y; As[c4+2][r] = v.z; As[c4+3][r] = v.w;
        }
        // load B tile
        if (!BT) {
            #pragma unroll
            for (int rep = 0; rep < 2; rep++) {
                int f = tid + rep*256;
                int kr = f >> 5, nc4 = (f & 31) * 4;  // k 0..15, n 0..124
                *(float4*)&Bs[kr][nc4] =
                    *(const float4*)(B + (size_t)(k0 + kr)*N + n0 + nc4);
            }
        } else {
            #pragma unroll
            for (int rep = 0; rep < 2; rep++) {
                int f = tid + rep*256;
                int nr = f >> 2, kc4 = (f & 3) * 4;   // n 0..127, k 0..12
                float4 v = make_float4(0.f, 0.f, 0.f, 0.f);
                if (n0 + nr < N)
                    v = *(const float4*)(B + (size_t)(n0 + nr)*K + k0 + kc4);
                Bs[kc4+0][nr] = v.x; Bs[kc4+1][nr] = v.y;
                Bs[kc4+2][nr] = v.z; Bs[kc4+3][nr] = v.w;
            }
        }
        __syncthreads();

        #pragma unroll
        for (int kk = 0; kk < 16; kk++) {
            float4 a0 = *(const float4*)&As[kk][ty*4];
            float4 a1 = *(const float4*)&As[kk][64 + ty*4];
            float4 b0 = *(const float4*)&Bs[kk][tx*4];
            float4 b1 = *(const float4*)&Bs[kk][64 + tx*4];
            float ar[8] = {a0.x,a0.y,a0.z,a0.w,a1.x,a1.y,a1.z,a1.w};
            float br[8] = {b0.x,b0.y,b0.z,b0.w,b1.x,b1.y,b1.z,b1.w};
            #pragma unroll
            for (int i = 0; i < 8; i++)
                #pragma unroll
                for (int j = 0; j < 8; j++)
                    acc[i][j] = fmaf(ar[i], br[j], acc[i][j]);
        }
        __syncthreads();
    }

    // epilogue
    #pragma unroll
    for (int i = 0; i < 8; i++) {
        int row = m0 + ((i < 4) ? (ty*4 + i) : (64 + ty*4 + i - 4));
        #pragma unroll
        for (int j = 0; j < 8; j++) {
            int col = n0 + ((j < 4) ? (tx*4 + j) : (64 + tx*4 + j - 4));
            if (col >= N) continue;
            float c = acc[i][j];
            if (EPI >= 1) c += bias[col];
            if (EPI == 2) c = 0.5f * c * (1.0f + erff(c * 0.70710678118654752f));
            if (EPI == 3) c += res[(size_t)row*N + col];
            C[(size_t)row*N + col] = c;
        }
    }
}

// ---------------- launch ----------------
extern "C" void kernel_launch(void* const* d_in, const int* in_sizes, int n_in,
                              void* d_out, int out_size) {
    const int*   idx    = (const int*)  d_in[0];
    const float* wte    = (const float*)d_in[1];
    const float* wpe    = (const float*)d_in[2];
    const float* ln1_g  = (const float*)d_in[3];
    const float* ln1_b  = (const float*)d_in[4];
    const float* attn_w = (const float*)d_in[5];
    const float* attn_b = (const float*)d_in[6];
    const float* proj_w = (const float*)d_in[7];
    const float* proj_b = (const float*)d_in[8];
    const float* ln2_g  = (const float*)d_in[9];
    const float* ln2_b  = (const float*)d_in[10];
    const float* fc_w   = (const float*)d_in[11];
    const float* fc_b   = (const float*)d_in[12];
    const float* fcp_w  = (const float*)d_in[13];
    const float* fcp_b  = (const float*)d_in[14];
    const float* lnf_g  = (const float*)d_in[15];
    const float* lnf_b  = (const float*)d_in[16];
    float* out = (float*)d_out;

    float *x, *xln, *qkv, *q, *k, *v, *y, *h4;
    cudaGetSymbolAddress((void**)&x,   g_x);
    cudaGetSymbolAddress((void**)&xln, g_xln);
    cudaGetSymbolAddress((void**)&qkv, g_qkv);
    cudaGetSymbolAddress((void**)&q,   g_q);
    cudaGetSymbolAddress((void**)&k,   g_k);
    cudaGetSymbolAddress((void**)&v,   g_v);
    cudaGetSymbolAddress((void**)&y,   g_y);
    cudaGetSymbolAddress((void**)&h4,  g_h4);

    embed_k<<<(M_*E_ + 255)/256, 256>>>(idx, wte, wpe, x);

    for (int l = 0; l < L_; l++) {
        ln_k<<<M_, 256>>>(x, ln1_g + l*E_, ln1_b + l*E_, xln);
        sgemm_k<1,false><<<dim3(3*E_/128, M_/128), 256>>>(
            xln, attn_w + (size_t)l*E_*3*E_, attn_b + l*3*E_, nullptr,
            qkv, M_, 3*E_, E_);
        split_k<<<(M_*3*E_ + 255)/256, 256>>>(qkv, q, k, v);
        attn_k<<<dim3(T_, B_*H_), 128>>>(q, k, v, y);
        sgemm_k<3,false><<<dim3(E_/128, M_/128), 256>>>(
            y, proj_w + (size_t)l*E_*E_, proj_b + l*E_, x,
            x, M_, E_, E_);
        ln_k<<<M_, 256>>>(x, ln2_g + l*E_, ln2_b + l*E_, xln);
        sgemm_k<2,false><<<dim3(4*E_/128, M_/128), 256>>>(
            xln, fc_w + (size_t)l*E_*4*E_, fc_b + l*4*E_, nullptr,
            h4, M_, 4*E_, E_);
        sgemm_k<3,false><<<dim3(E_/128, M_/128), 256>>>(
            h4, fcp_w + (size_t)l*4*E_*E_, fcp_b + l*E_, x,
            x, M_, E_, 4*E_);
    }

    ln_k<<<M_, 256>>>(x, lnf_g, lnf_b, xln);
    // logits = xln @ wte^T   (wte is [V,E] row-major -> BT=true)
    sgemm_k<0,true><<<dim3((V_ + 127)/128, M_/128), 256>>>(
        xln, wte, nullptr, nullptr, out, M_, V_, E_);
}

// round 4
// speedup vs baseline: 2.1056x; 2.1056x over previous
#include <cuda_runtime.h>
#include <cuda_bf16.h>
#include <math.h>
#include <stdint.h>

#define E_ 768
#define L_ 12
#define H_ 12
#define D_ 64
#define B_ 2
#define T_ 1024
#define V_ 50257
#define M_ (B_*T_)           // 2048 rows

// ---------------- scratch (static device globals; no allocs) ----------------
__device__ float g_x  [M_*E_];
__device__ float g_xln[M_*E_];
__device__ float g_qkv[M_*3*E_];
__device__ float g_q  [B_*H_*T_*D_];
__device__ float g_k  [B_*H_*T_*D_];
__device__ float g_v  [B_*H_*T_*D_];
__device__ float g_y  [M_*E_];
__device__ float g_h4 [M_*4*E_];
// transposed weights: [N,K] K-major for the GEMM B operand
__device__ float g_attnT[L_*3*E_*E_];
__device__ float g_projT[L_*E_*E_];
__device__ float g_fcT  [L_*4*E_*E_];
__device__ float g_fcpT [L_*4*E_*E_];

// ---------------- helpers ----------------
__device__ __forceinline__ uint32_t cvta_smem(const void* p){
    uint32_t a;
    asm("{.reg .u64 t; cvta.to.shared.u64 t, %1; cvt.u32.u64 %0, t;}" : "=r"(a) : "l"(p));
    return a;
}
__device__ __forceinline__ void ldsm4(uint32_t* r, uint32_t addr){
    asm volatile("ldmatrix.sync.aligned.m8n8.x4.shared.b16 {%0,%1,%2,%3}, [%4];"
        : "=r"(r[0]),"=r"(r[1]),"=r"(r[2]),"=r"(r[3]) : "r"(addr));
}
__device__ __forceinline__ void mma16816(float* d, const uint32_t* a, const uint32_t* b){
    asm volatile("mma.sync.aligned.m16n8k16.row.col.f32.bf16.bf16.f32 "
        "{%0,%1,%2,%3}, {%4,%5,%6,%7}, {%8,%9}, {%0,%1,%2,%3};"
        : "+f"(d[0]),"+f"(d[1]),"+f"(d[2]),"+f"(d[3])
        : "r"(a[0]),"r"(a[1]),"r"(a[2]),"r"(a[3]), "r"(b[0]),"r"(b[1]));
}
__device__ __forceinline__ uint32_t packbf(float a, float b){
    __nv_bfloat162 t = __floats2bfloat162_rn(a, b);
    return *reinterpret_cast<uint32_t*>(&t);
}
__device__ __forceinline__ float bfhi(float a){
    return __bfloat162float(__float2bfloat16_rn(a));
}
__device__ __forceinline__ void stsv4(uint32_t addr, uint32_t a, uint32_t b, uint32_t c, uint32_t d){
    asm volatile("st.shared.v4.b32 [%0], {%1,%2,%3,%4};"
        :: "r"(addr), "r"(a), "r"(b), "r"(c), "r"(d) : "memory");
}
__device__ __forceinline__ float gelu_f(float v){
    return 0.5f * v * (1.0f + erff(v * 0.70710678118654752f));
}

// ---------------- bf16-split mma.sync GEMM: 128x128x32, double-buffered ------
#define ROWB 80                 // smem row stride (bytes): 32 bf16 + 16B pad
#define BUF_A_H 0
#define BUF_A_L 10240
#define BUF_B_H 20480
#define BUF_B_L 30720
#define STAGEB  40960
#define GEMM_SMEM (2*STAGEB)    // 81920

// convert 8 consecutive floats (2 float4) to hi/lo bf16 chunks and store
__device__ __forceinline__ void store_hilo(uint32_t ah, uint32_t al, float4 x, float4 y){
    uint32_t h0 = packbf(x.x, x.y), h1 = packbf(x.z, x.w);
    uint32_t h2 = packbf(y.x, y.y), h3 = packbf(y.z, y.w);
    float l0 = x.x - bfhi(x.x), l1 = x.y - bfhi(x.y);
    float l2 = x.z - bfhi(x.z), l3 = x.w - bfhi(x.w);
    float l4 = y.x - bfhi(y.x), l5 = y.y - bfhi(y.y);
    float l6 = y.z - bfhi(y.z), l7 = y.w - bfhi(y.w);
    stsv4(ah, h0, h1, h2, h3);
    stsv4(al, packbf(l0,l1), packbf(l2,l3), packbf(l4,l5), packbf(l6,l7));
}

// EPI: 0 none, 1 +bias, 2 gelu(+bias), 3 +bias+residual
template<int EPI>
__global__ void __launch_bounds__(256, 1)
gemm_tc(const float* __restrict__ A, const float* __restrict__ Bm,
        const float* __restrict__ bias, const float* __restrict__ res,
        float* __restrict__ C, int M, int N, int K) {
    extern __shared__ char smraw[];
    const uint32_t sb = cvta_smem(smraw);
    const int tid = threadIdx.x;
    const int lane = tid & 31, wid = tid >> 5;
    const int wm = wid & 3, wn = wid >> 2;            // 4 x 2 warp grid
    const int m0 = blockIdx.x * 128, n0 = blockIdx.y * 128;
    const int nkb = K >> 5;

    float acc[2][8][4];
    #pragma unroll
    for (int i = 0; i < 2; i++)
        #pragma unroll
        for (int j = 0; j < 8; j++)
            #pragma unroll
            for (int t = 0; t < 4; t++) acc[i][j][t] = 0.f;

    // per-thread global-load coordinates: 2 chunks (16B-bf16 units = 8 floats)
    const int ar0 = tid >> 2,          ac0 = tid & 3;
    const int ar1 = (tid + 256) >> 2,  ac1 = (tid + 256) & 3;
    const float* Abase = A + (size_t)m0 * K;
    const float* Bbase = Bm + (size_t)n0 * K;
    const bool bg0 = (n0 + ar0) < N, bg1 = (n0 + ar1) < N;
    const float4 z4 = make_float4(0.f, 0.f, 0.f, 0.f);

    float4 v[8];
    // prologue: load tile 0
    {
        const float* p;
        p = Abase + (size_t)ar0*K + ac0*8;           v[0]=((const float4*)p)[0]; v[1]=((const float4*)p)[1];
        p = Abase + (size_t)ar1*K + ac1*8;           v[2]=((const float4*)p)[0]; v[3]=((const float4*)p)[1];
        p = Bbase + (size_t)ar0*K + ac0*8;           v[4]=bg0?((const float4*)p)[0]:z4; v[5]=bg0?((const float4*)p)[1]:z4;
        p = Bbase + (size_t)ar1*K + ac1*8;           v[6]=bg1?((const float4*)p)[0]:z4; v[7]=bg1?((const float4*)p)[1]:z4;
        uint32_t st = sb;
        uint32_t o0 = (uint32_t)(ar0*ROWB + ac0*16), o1 = (uint32_t)(ar1*ROWB + ac1*16);
        store_hilo(st + BUF_A_H + o0, st + BUF_A_L + o0, v[0], v[1]);
        store_hilo(st + BUF_A_H + o1, st + BUF_A_L + o1, v[2], v[3]);
        store_hilo(st + BUF_B_H + o0, st + BUF_B_L + o0, v[4], v[5]);
        store_hilo(st + BUF_B_H + o1, st + BUF_B_L + o1, v[6], v[7]);
    }

    for (int kb = 0; kb < nkb; kb++) {
        __syncthreads();
        const uint32_t st = sb + (uint32_t)(kb & 1) * STAGEB;
        const bool more = (kb + 1 < nkb);
        if (more) {
            const int ko = (kb + 1) * 32;
            const float* p;
            p = Abase + (size_t)ar0*K + ko + ac0*8;  v[0]=((const float4*)p)[0]; v[1]=((const float4*)p)[1];
            p = Abase + (size_t)ar1*K + ko + ac1*8;  v[2]=((const float4*)p)[0]; v[3]=((const float4*)p)[1];
            p = Bbase + (size_t)ar0*K + ko + ac0*8;  v[4]=bg0?((const float4*)p)[0]:z4; v[5]=bg0?((const float4*)p)[1]:z4;
            p = Bbase + (size_t)ar1*K + ko + ac1*8;  v[6]=bg1?((const float4*)p)[0]:z4; v[7]=bg1?((const float4*)p)[1]:z4;
        }
        // ---- compute on stage st: 2 k-steps of k16 ----
        #pragma unroll
        for (int ks = 0; ks < 2; ks++) {
            uint32_t ah[2][4], al[2][4], bhf[8][2], blf[8][2];
            #pragma unroll
            for (int mi = 0; mi < 2; mi++) {
                int row = wm*32 + mi*16 + (lane & 15);
                int ch  = 2*ks + (lane >> 4);
                uint32_t off = (uint32_t)(row*ROWB + ch*16);
                ldsm4(ah[mi], st + BUF_A_H + off);
                ldsm4(al[mi], st + BUF_A_L + off);
            }
            #pragma unroll
            for (int p2 = 0; p2 < 4; p2++) {
                int nr = wn*64 + p2*16 + (lane & 7) + ((lane >> 4) << 3);
                int ch = 2*ks + ((lane >> 3) & 1);
                uint32_t off = (uint32_t)(nr*ROWB + ch*16);
                uint32_t t[4];
                ldsm4(t, st + BUF_B_H + off);
                bhf[2*p2][0]=t[0]; bhf[2*p2][1]=t[1]; bhf[2*p2+1][0]=t[2]; bhf[2*p2+1][1]=t[3];
                ldsm4(t, st + BUF_B_L + off);
                blf[2*p2][0]=t[0]; blf[2*p2][1]=t[1]; blf[2*p2+1][0]=t[2]; blf[2*p2+1][1]=t[3];
            }
            #pragma unroll
            for (int mi = 0; mi < 2; mi++)
                #pragma unroll
                for (int nj = 0; nj < 8; nj++) {
                    mma16816(acc[mi][nj], ah[mi], bhf[nj]);
                    mma16816(acc[mi][nj], ah[mi], blf[nj]);
                    mma16816(acc[mi][nj], al[mi], bhf[nj]);
                }
        }
        if (more) {
            const uint32_t sn = sb + (uint32_t)((kb + 1) & 1) * STAGEB;
            uint32_t o0 = (uint32_t)(ar0*ROWB + ac0*16), o1 = (uint32_t)(ar1*ROWB + ac1*16);
            store_hilo(sn + BUF_A_H + o0, sn + BUF_A_L + o0, v[0], v[1]);
            store_hilo(sn + BUF_A_H + o1, sn + BUF_A_L + o1, v[2], v[3]);
            store_hilo(sn + BUF_B_H + o0, sn + BUF_B_L + o0, v[4], v[5]);
            store_hilo(sn + BUF_B_H + o1, sn + BUF_B_L + o1, v[6], v[7]);
        }
    }

    // ---- epilogue (alignment-safe: vector store only when N is even) ----
    const int mrow = m0 + wm*32 + (lane >> 2);
    const int ncol = n0 + wn*64 + 2*(lane & 3);
    const bool vec_ok = ((N & 1) == 0);
    #pragma unroll
    for (int mi = 0; mi < 2; mi++) {
        #pragma unroll
        for (int nj = 0; nj < 8; nj++) {
            int c = ncol + nj*8;
            #pragma unroll
            for (int h2 = 0; h2 < 2; h2++) {
                int rr = mrow + mi*16 + h2*8;
                float v0 = acc[mi][nj][h2*2], v1 = acc[mi][nj][h2*2+1];
                if (vec_ok && c + 1 < N) {
                    if (EPI >= 1) { v0 += bias[c]; v1 += bias[c+1]; }
                    if (EPI == 2) { v0 = gelu_f(v0); v1 = gelu_f(v1); }
                    if (EPI == 3) {
                        v0 += res[(size_t)rr*N + c]; v1 += res[(size_t)rr*N + c + 1];
                    }
                    float2 o; o.x = v0; o.y = v1;
                    *(float2*)(C + (size_t)rr*N + c) = o;
                } else {
                    if (c < N) {
                        if (EPI >= 1) v0 += bias[c];
                        if (EPI == 2) v0 = gelu_f(v0);
                        if (EPI == 3) v0 += res[(size_t)rr*N + c];
                        C[(size_t)rr*N + c] = v0;
                    }
                    if (c + 1 < N) {
                        if (EPI >= 1) v1 += bias[c+1];
                        if (EPI == 2) v1 = gelu_f(v1);
                        if (EPI == 3) v1 += res[(size_t)rr*N + c + 1];
                        C[(size_t)rr*N + c + 1] = v1;
                    }
                }
            }
        }
    }
}

// ---------------- flash attention: 64q x 64k tiles, fp32 ----------------
#define FA_STRIDE 68
#define FA_SMEM (3*64*FA_STRIDE*4)   // Ks, Vs, Ps = 52224 bytes

__global__ void __launch_bounds__(256)
flash_k(const float* __restrict__ qh, const float* __restrict__ kh,
        const float* __restrict__ vh, float* __restrict__ y) {
    extern __shared__ float fs[];
    float* Ks = fs;
    float* Vs = fs + 64*FA_STRIDE;
    float* Ps = fs + 2*64*FA_STRIDE;
    const int qt = blockIdx.x, bh = blockIdx.y;
    const int tid = threadIdx.x;
    const int r = tid >> 2, g = tid & 3;
    const int q0 = qt * 64;

    // stage Q tile into Ps, then pull own row into registers
    const float* Qg = qh + ((size_t)bh*T_ + q0) * 64;
    #pragma unroll
    for (int i = 0; i < 4; i++) {
        int j = tid + i*256;
        int row = j >> 4, c4 = (j & 15) * 4;
        *(float4*)&Ps[row*FA_STRIDE + c4] = *(const float4*)(Qg + row*64 + c4);
    }
    __syncthreads();
    float Qr[64];
    #pragma unroll
    for (int d4 = 0; d4 < 16; d4++) {
        float4 t = *(const float4*)&Ps[r*FA_STRIDE + d4*4];
        Qr[d4*4+0] = t.x; Qr[d4*4+1] = t.y; Qr[d4*4+2] = t.z; Qr[d4*4+3] = t.w;
    }

    float m = -1e30f, l = 0.f, O[16];
    #pragma unroll
    for (int i = 0; i < 16; i++) O[i] = 0.f;

    for (int kt = 0; kt <= qt; kt++) {
        __syncthreads();
        const float* Kg = kh + ((size_t)bh*T_ + kt*64) * 64;
        const float* Vg = vh + ((size_t)bh*T_ + kt*64) * 64;
        #pragma unroll
        for (int i = 0; i < 4; i++) {
            int j = tid + i*256;
            int row = j >> 4, c4 = (j & 15) * 4;
            *(float4*)&Ks[row*FA_STRIDE + c4] = *(const float4*)(Kg + row*64 + c4);
            *(float4*)&Vs[row*FA_STRIDE + c4] = *(const float4*)(Vg + row*64 + c4);
        }
        __syncthreads();

        float s[16];
        #pragma unroll
        for (int jj = 0; jj < 16; jj++) {
            int j = jj*4 + g;
            const float* kr = &Ks[j*FA_STRIDE];
            float a = 0.f;
            #pragma unroll
            for (int d4 = 0; d4 < 16; d4++) {
                float4 kv = *(const float4*)(kr + d4*4);
                a = fmaf(Qr[4*d4+0], kv.x, a);
                a = fmaf(Qr[4*d4+1], kv.y, a);
                a = fmaf(Qr[4*d4+2], kv.z, a);
                a = fmaf(Qr[4*d4+3], kv.w, a);
            }
            a *= 0.125f;
            if (kt == qt && j > r) a = -1e30f;
            s[jj] = a;
        }
        float tm = s[0];
        #pragma unroll
        for (int jj = 1; jj < 16; jj++) tm = fmaxf(tm, s[jj]);
        tm = fmaxf(tm, __shfl_xor_sync(0xffffffffu, tm, 1));
        tm = fmaxf(tm, __shfl_xor_sync(0xffffffffu, tm, 2));
        float nm = fmaxf(m, tm);
        float alpha = __expf(m - nm);
        float ls = 0.f;
        #pragma unroll
        for (int jj = 0; jj < 16; jj++) {
            float p = __expf(s[jj] - nm);
            Ps[r*FA_STRIDE + jj*4 + g] = p;
            ls += p;
        }
        ls += __shfl_xor_sync(0xffffffffu, ls, 1);
        ls += __shfl_xor_sync(0xffffffffu, ls, 2);
        l = l * alpha + ls;
        m = nm;
        #pragma unroll
        for (int i = 0; i < 16; i++) O[i] *= alpha;
        __syncthreads();
        #pragma unroll 4
        for (int j = 0; j < 64; j++) {
            float p = Ps[r*FA_STRIDE + j];
            const float* vr = &Vs[j*FA_STRIDE + g*16];
            #pragma unroll
            for (int d4 = 0; d4 < 4; d4++) {
                float4 vv = *(const float4*)(vr + d4*4);
                O[d4*4+0] = fmaf(p, vv.x, O[d4*4+0]);
                O[d4*4+1] = fmaf(p, vv.y, O[d4*4+1]);
                O[d4*4+2] = fmaf(p, vv.z, O[d4*4+2]);
                O[d4*4+3] = fmaf(p, vv.w, O[d4*4+3]);
            }
        }
    }

    const float inv = 1.f / l;
    const int b = bh / H_, h = bh % H_;
    float* yr = y + ((size_t)(b*T_ + q0 + r)) * E_ + h*64 + g*16;
    #pragma unroll
    for (int d4 = 0; d4 < 4; d4++) {
        float4 o;
        o.x = O[d4*4+0]*inv; o.y = O[d4*4+1]*inv;
        o.z = O[d4*4+2]*inv; o.w = O[d4*4+3]*inv;
        *(float4*)(yr + d4*4) = o;
    }
}

// ---------------- weight transpose: W[K,N] -> WT[N,K], per layer in z --------
__global__ void transpose_k(const float* __restrict__ W, float* __restrict__ WT,
                            int K, int N) {
    __shared__ float t[32][33];
    const size_t lstride = (size_t)K * N;
    const float* Wl = W + lstride * blockIdx.z;
    float* WTl = WT + lstride * blockIdx.z;
    int n0 = blockIdx.x * 32, k0 = blockIdx.y * 32;
    int x = threadIdx.x, y = threadIdx.y;   // 32 x 8
    #pragma unroll
    for (int i = 0; i < 32; i += 8)
        t[y + i][x] = Wl[(size_t)(k0 + y + i) * N + n0 + x];
    __syncthreads();
    #pragma unroll
    for (int i = 0; i < 32; i += 8)
        WTl[(size_t)(n0 + y + i) * K + k0 + x] = t[x][y + i];
}

// ---------------- embedding ----------------
__global__ void embed_k(const int* __restrict__ idx, const float* __restrict__ wte,
                        const float* __restrict__ wpe, float* __restrict__ x) {
    int i = blockIdx.x * blockDim.x + threadIdx.x;
    if (i >= M_*E_) return;
    int row = i / E_, e = i % E_;
    int t = row & (T_-1);
    x[i] = wte[(size_t)idx[row]*E_ + e] + wpe[t*E_ + e];
}

// ---------------- layernorm (1 block / row) ----------------
__global__ void ln_k(const float* __restrict__ x, const float* __restrict__ g,
                     const float* __restrict__ b, float* __restrict__ o) {
    int row = blockIdx.x;
    int tid = threadIdx.x;
    const float* xr = x + (size_t)row*E_;
    __shared__ float s1[256], s2[256];
    float a = 0.f, q = 0.f;
    for (int e = tid; e < E_; e += 256) { float v = xr[e]; a += v; q += v*v; }
    s1[tid] = a; s2[tid] = q; __syncthreads();
    for (int off = 128; off > 0; off >>= 1) {
        if (tid < off) { s1[tid] += s1[tid+off]; s2[tid] += s2[tid+off]; }
        __syncthreads();
    }
    float mu  = s1[0] * (1.f/E_);
    float var = s2[0] * (1.f/E_) - mu*mu;
    float inv = rsqrtf(var + 1e-5f);
    for (int e = tid; e < E_; e += 256)
        o[(size_t)row*E_ + e] = (xr[e] - mu) * inv * g[e] + b[e];
}

// ---------------- split qkv -> per-head [B,H,T,D] ----------------
__global__ void split_k(const float* __restrict__ qkv, float* __restrict__ q,
                        float* __restrict__ k, float* __restrict__ v) {
    int i = blockIdx.x * blockDim.x + threadIdx.x;
    if (i >= M_*3*E_) return;
    int row = i / (3*E_), col = i % (3*E_);
    int which = col / E_;  int e = col % E_;
    int h = e >> 6, d = e & 63;
    int b = row >> 10, t = row & (T_-1);
    float val = qkv[i];
    float* dst = (which == 0) ? q : (which == 1) ? k : v;
    dst[(((b*H_ + h)*T_) + t)*D_ + d] = val;
}

// ---------------- launch ----------------
extern "C" void kernel_launch(void* const* d_in, const int* in_sizes, int n_in,
                              void* d_out, int out_size) {
    const int*   idx    = (const int*)  d_in[0];
    const float* wte    = (const float*)d_in[1];
    const float* wpe    = (const float*)d_in[2];
    const float* ln1_g  = (const float*)d_in[3];
    const float* ln1_b  = (const float*)d_in[4];
    const float* attn_w = (const float*)d_in[5];
    const float* attn_b = (const float*)d_in[6];
    const float* proj_w = (const float*)d_in[7];
    const float* proj_b = (const float*)d_in[8];
    const float* ln2_g  = (const float*)d_in[9];
    const float* ln2_b  = (const float*)d_in[10];
    const float* fc_w   = (const float*)d_in[11];
    const float* fc_b   = (const float*)d_in[12];
    const float* fcp_w  = (const float*)d_in[13];
    const float* fcp_b  = (const float*)d_in[14];
    const float* lnf_g  = (const float*)d_in[15];
    const float* lnf_b  = (const float*)d_in[16];
    float* out = (float*)d_out;

    float *x, *xln, *qkv, *q, *k, *v, *y, *h4;
    float *attnT, *projT, *fcT, *fcpT;
    cudaGetSymbolAddress((void**)&x,   g_x);
    cudaGetSymbolAddress((void**)&xln, g_xln);
    cudaGetSymbolAddress((void**)&qkv, g_qkv);
    cudaGetSymbolAddress((void**)&q,   g_q);
    cudaGetSymbolAddress((void**)&k,   g_k);
    cudaGetSymbolAddress((void**)&v,   g_v);
    cudaGetSymbolAddress((void**)&y,   g_y);
    cudaGetSymbolAddress((void**)&h4,  g_h4);
    cudaGetSymbolAddress((void**)&attnT, g_attnT);
    cudaGetSymbolAddress((void**)&projT, g_projT);
    cudaGetSymbolAddress((void**)&fcT,   g_fcT);
    cudaGetSymbolAddress((void**)&fcpT,  g_fcpT);

    cudaFuncSetAttribute(gemm_tc<0>, cudaFuncAttributeMaxDynamicSharedMemorySize, GEMM_SMEM);
    cudaFuncSetAttribute(gemm_tc<1>, cudaFuncAttributeMaxDynamicSharedMemorySize, GEMM_SMEM);
    cudaFuncSetAttribute(gemm_tc<2>, cudaFuncAttributeMaxDynamicSharedMemorySize, GEMM_SMEM);
    cudaFuncSetAttribute(gemm_tc<3>, cudaFuncAttributeMaxDynamicSharedMemorySize, GEMM_SMEM);
    cudaFuncSetAttribute(flash_k,    cudaFuncAttributeMaxDynamicSharedMemorySize, FA_SMEM);

    dim3 tb(32, 8);
    transpose_k<<<dim3(3*E_/32, E_/32, L_), tb>>>(attn_w, attnT, E_, 3*E_);
    transpose_k<<<dim3(E_/32,   E_/32, L_), tb>>>(proj_w, projT, E_, E_);
    transpose_k<<<dim3(4*E_/32, E_/32, L_), tb>>>(fc_w,   fcT,   E_, 4*E_);
    transpose_k<<<dim3(E_/32, 4*E_/32, L_), tb>>>(fcp_w,  fcpT,  4*E_, E_);

    embed_k<<<(M_*E_ + 255)/256, 256>>>(idx, wte, wpe, x);

    for (int l = 0; l < L_; l++) {
        ln_k<<<M_, 256>>>(x, ln1_g + l*E_, ln1_b + l*E_, xln);
        gemm_tc<1><<<dim3(M_/128, 3*E_/128), 256, GEMM_SMEM>>>(
            xln, attnT + (size_t)l*3*E_*E_, attn_b + l*3*E_, nullptr,
            qkv, M_, 3*E_, E_);
        split_k<<<(M_*3*E_ + 255)/256, 256>>>(qkv, q, k, v);
        flash_k<<<dim3(T_/64, B_*H_), 256, FA_SMEM>>>(q, k, v, y);
        gemm_tc<3><<<dim3(M_/128, E_/128), 256, GEMM_SMEM>>>(
            y, projT + (size_t)l*E_*E_, proj_b + l*E_, x,
            x, M_, E_, E_);
        ln_k<<<M_, 256>>>(x, ln2_g + l*E_, ln2_b + l*E_, xln);
        gemm_tc<2><<<dim3(M_/128, 4*E_/128), 256, GEMM_SMEM>>>(
            xln, fcT + (size_t)l*4*E_*E_, fc_b + l*4*E_, nullptr,
            h4, M_, 4*E_, E_);
        gemm_tc<3><<<dim3(M_/128, E_/128), 256, GEMM_SMEM>>>(
            h4, fcpT + (size_t)l*4*E_*E_, fcp_b + l*E_, x,
            x, M_, E_, 4*E_);
    }

    ln_k<<<M_, 256>>>(x, lnf_g, lnf_b, xln);
    // logits = xln @ wte^T : wte is [V,E] row-major = [N,K] K-major already
    gemm_tc<0><<<dim3(M_/128, (V_ + 127)/128), 256, GEMM_SMEM>>>(
        xln, wte, nullptr, nullptr, out, M_, V_, E_);
}

// round 5
// speedup vs baseline: 2.1461x; 1.0192x over previous
#include <cuda_runtime.h>
#include <cuda_bf16.h>
#include <math.h>
#include <stdint.h>

#define E_ 768
#define L_ 12
#define H_ 12
#define D_ 64
#define B_ 2
#define T_ 1024
#define V_ 50257
#define VP_ 50304            // padded to multiple of 128
#define M_ (B_*T_)           // 2048 rows
#define BHTD_ (B_*H_*T_*D_)  // 1572864

// ---------------- scratch (static device globals; no allocs) ----------------
__device__ float g_x   [M_*E_];             // residual stream (fp32)
__device__ float g_qkvh[3*BHTD_];           // q | k | v in [B,H,T,D]
// bf16 hi/lo activations
__device__ __nv_bfloat16 g_xh [M_*E_],  g_xl [M_*E_];     // LN outputs
__device__ __nv_bfloat16 g_yh [M_*E_],  g_yl [M_*E_];     // attention out
__device__ __nv_bfloat16 g_h4h[M_*4*E_],g_h4l[M_*4*E_];   // gelu out
// bf16 hi/lo transposed weights: [N,K] K-major
__device__ __nv_bfloat16 g_attnTh[L_*3*E_*E_], g_attnTl[L_*3*E_*E_];
__device__ __nv_bfloat16 g_projTh[L_*E_*E_],   g_projTl[L_*E_*E_];
__device__ __nv_bfloat16 g_fcTh  [L_*4*E_*E_], g_fcTl  [L_*4*E_*E_];
__device__ __nv_bfloat16 g_fcpTh [L_*4*E_*E_], g_fcpTl [L_*4*E_*E_];
__device__ __nv_bfloat16 g_wteh  [VP_*E_],     g_wtel  [VP_*E_];

// ---------------- helpers ----------------
__device__ __forceinline__ uint32_t cvta_smem(const void* p){
    uint32_t a;
    asm("{.reg .u64 t; cvta.to.shared.u64 t, %1; cvt.u32.u64 %0, t;}" : "=r"(a) : "l"(p));
    return a;
}
__device__ __forceinline__ void ldsm4(uint32_t* r, uint32_t addr){
    asm volatile("ldmatrix.sync.aligned.m8n8.x4.shared.b16 {%0,%1,%2,%3}, [%4];"
        : "=r"(r[0]),"=r"(r[1]),"=r"(r[2]),"=r"(r[3]) : "r"(addr));
}
__device__ __forceinline__ void mma16816(float* d, const uint32_t* a, const uint32_t* b){
    asm volatile("mma.sync.aligned.m16n8k16.row.col.f32.bf16.bf16.f32 "
        "{%0,%1,%2,%3}, {%4,%5,%6,%7}, {%8,%9}, {%0,%1,%2,%3};"
        : "+f"(d[0]),"+f"(d[1]),"+f"(d[2]),"+f"(d[3])
        : "r"(a[0]),"r"(a[1]),"r"(a[2]),"r"(a[3]), "r"(b[0]),"r"(b[1]));
}
__device__ __forceinline__ void cpa16(uint32_t s, const void* g){
    asm volatile("cp.async.cg.shared.global [%0], [%1], 16;" :: "r"(s), "l"(g));
}
__device__ __forceinline__ float gelu_f(float v){
    return 0.5f * v * (1.0f + erff(v * 0.70710678118654752f));
}
__device__ __forceinline__ void split_bf(float v, __nv_bfloat16& h, __nv_bfloat16& l){
    h = __float2bfloat16_rn(v);
    l = __float2bfloat16_rn(v - __bfloat162float(h));
}

// ---------------- bf16-split mma.sync GEMM: 128x128x32, cp.async 3-stage -----
#define ROWB 80                 // smem row stride (bytes): 64B data + 16B pad
#define BUF_AH 0
#define BUF_AL 10240
#define BUF_BH 20480
#define BUF_BL 30720
#define STAGEB 40960
#define NS 3
#define GEMM_SMEM (NS*STAGEB)   // 122880

// EPI: 0 none, 1 +bias, 2 gelu(+bias), 3 +bias+residual
// OUT: 0 fp32 C, 1 bf16 hi/lo (Ch,Cl), 2 qkv head-scatter into C (q|k|v)
template<int EPI, int OUT>
__global__ void __launch_bounds__(256, 1)
gemm_bf(const __nv_bfloat16* __restrict__ Ahg, const __nv_bfloat16* __restrict__ Alg,
        const __nv_bfloat16* __restrict__ Bhg, const __nv_bfloat16* __restrict__ Blg,
        const float* __restrict__ bias, const float* __restrict__ res,
        float* __restrict__ C, __nv_bfloat16* __restrict__ Ch,
        __nv_bfloat16* __restrict__ Cl, int M, int N, int K) {
    extern __shared__ char smraw[];
    const uint32_t sb = cvta_smem(smraw);
    const int tid = threadIdx.x;
    const int lane = tid & 31, wid = tid >> 5;
    const int wm = wid & 3, wn = wid >> 2;            // 4 x 2 warp grid
    const int m0 = blockIdx.x * 128, n0 = blockIdx.y * 128;
    const int nkb = K >> 5;

    float acc[2][8][4];
    #pragma unroll
    for (int i = 0; i < 2; i++)
        #pragma unroll
        for (int j = 0; j < 8; j++)
            #pragma unroll
            for (int t = 0; t < 4; t++) acc[i][j][t] = 0.f;

    // loader: 512 16B-chunks per tile / 256 threads = 2 per thread per tile
    const int r0 = tid >> 2,         c0 = tid & 3;
    const int r1 = (tid+256) >> 2,   c1 = (tid+256) & 3;
    const uint32_t so0 = (uint32_t)(r0*ROWB + c0*16);
    const uint32_t so1 = (uint32_t)(r1*ROWB + c1*16);

    auto load_stage = [&](int kb){
        const uint32_t st = sb + (uint32_t)(kb % NS) * STAGEB;
        const int k0 = kb * 32;
        const size_t a0 = (size_t)(m0+r0)*K + k0 + c0*8;
        const size_t a1 = (size_t)(m0+r1)*K + k0 + c1*8;
        const size_t b0 = (size_t)(n0+r0)*K + k0 + c0*8;
        const size_t b1 = (size_t)(n0+r1)*K + k0 + c1*8;
        cpa16(st+BUF_AH+so0, Ahg+a0);  cpa16(st+BUF_AH+so1, Ahg+a1);
        cpa16(st+BUF_AL+so0, Alg+a0);  cpa16(st+BUF_AL+so1, Alg+a1);
        cpa16(st+BUF_BH+so0, Bhg+b0);  cpa16(st+BUF_BH+so1, Bhg+b1);
        cpa16(st+BUF_BL+so0, Blg+b0);  cpa16(st+BUF_BL+so1, Blg+b1);
    };

    load_stage(0);
    asm volatile("cp.async.commit_group;" ::: "memory");
    load_stage(1);
    asm volatile("cp.async.commit_group;" ::: "memory");

    for (int kb = 0; kb < nkb; kb++) {
        asm volatile("cp.async.wait_group 1;" ::: "memory");
        __syncthreads();
        if (kb + 2 < nkb) load_stage(kb + 2);
        asm volatile("cp.async.commit_group;" ::: "memory");

        const uint32_t st = sb + (uint32_t)(kb % NS) * STAGEB;
        #pragma unroll
        for (int ks = 0; ks < 2; ks++) {
            uint32_t ah[2][4], al[2][4], bhf[8][2], blf[8][2];
            #pragma unroll
            for (int mi = 0; mi < 2; mi++) {
                int row = wm*32 + mi*16 + (lane & 15);
                int ch  = 2*ks + (lane >> 4);
                uint32_t off = (uint32_t)(row*ROWB + ch*16);
                ldsm4(ah[mi], st + BUF_AH + off);
                ldsm4(al[mi], st + BUF_AL + off);
            }
            #pragma unroll
            for (int p2 = 0; p2 < 4; p2++) {
                int nr = wn*64 + p2*16 + (lane & 7) + ((lane >> 4) << 3);
                int ch = 2*ks + ((lane >> 3) & 1);
                uint32_t off = (uint32_t)(nr*ROWB + ch*16);
                uint32_t t[4];
                ldsm4(t, st + BUF_BH + off);
                bhf[2*p2][0]=t[0]; bhf[2*p2][1]=t[1]; bhf[2*p2+1][0]=t[2]; bhf[2*p2+1][1]=t[3];
                ldsm4(t, st + BUF_BL + off);
                blf[2*p2][0]=t[0]; blf[2*p2][1]=t[1]; blf[2*p2+1][0]=t[2]; blf[2*p2+1][1]=t[3];
            }
            #pragma unroll
            for (int mi = 0; mi < 2; mi++)
                #pragma unroll
                for (int nj = 0; nj < 8; nj++) {
                    mma16816(acc[mi][nj], ah[mi], bhf[nj]);
                    mma16816(acc[mi][nj], ah[mi], blf[nj]);
                    mma16816(acc[mi][nj], al[mi], bhf[nj]);
                }
        }
    }

    // ---- epilogue ----
    const int mrow = m0 + wm*32 + (lane >> 2);
    const int ncol = n0 + wn*64 + 2*(lane & 3);
    const bool vec_ok = ((N & 1) == 0);
    #pragma unroll
    for (int mi = 0; mi < 2; mi++) {
        #pragma unroll
        for (int nj = 0; nj < 8; nj++) {
            int c = ncol + nj*8;
            #pragma unroll
            for (int h2 = 0; h2 < 2; h2++) {
                int rr = mrow + mi*16 + h2*8;
                float v0 = acc[mi][nj][h2*2], v1 = acc[mi][nj][h2*2+1];
                if (EPI >= 1 && c < N)     v0 += bias[c];
                if (EPI >= 1 && c+1 < N)   v1 += bias[c+1];
                if (EPI == 2) { v0 = gelu_f(v0); v1 = gelu_f(v1); }
                if (OUT == 2) {
                    // qkv scatter: C = base of q|k|v, each [B,H,T,D]
                    int which = c / E_, e = c % E_;
                    int hh = e >> 6, d = e & 63;
                    int b = rr >> 10, t = rr & (T_-1);
                    float2 o; o.x = v0; o.y = v1;
                    *(float2*)(C + (size_t)which*BHTD_ +
                               (((size_t)(b*H_ + hh)*T_) + t)*D_ + d) = o;
                } else if (OUT == 1) {
                    if (EPI == 3) {
                        v0 += res[(size_t)rr*N + c]; v1 += res[(size_t)rr*N + c + 1];
                    }
                    __nv_bfloat16 h0, l0, h1, l1;
                    split_bf(v0, h0, l0); split_bf(v1, h1, l1);
                    __nv_bfloat162 hv; hv.x = h0; hv.y = h1;
                    __nv_bfloat162 lv; lv.x = l0; lv.y = l1;
                    *(__nv_bfloat162*)(Ch + (size_t)rr*N + c) = hv;
                    *(__nv_bfloat162*)(Cl + (size_t)rr*N + c) = lv;
                } else {
                    if (vec_ok && c + 1 < N) {
                        if (EPI == 3) {
                            v0 += res[(size_t)rr*N + c]; v1 += res[(size_t)rr*N + c + 1];
                        }
                        float2 o; o.x = v0; o.y = v1;
                        *(float2*)(C + (size_t)rr*N + c) = o;
                    } else {
                        if (c < N) {
                            if (EPI == 3) v0 += res[(size_t)rr*N + c];
                            C[(size_t)rr*N + c] = v0;
                        }
                        if (c + 1 < N) {
                            if (EPI == 3) v1 += res[(size_t)rr*N + c + 1];
                            C[(size_t)rr*N + c + 1] = v1;
                        }
                    }
                }
            }
        }
    }
}

// ---------------- flash attention: 64q x 64k tiles, fp32, bf16 hi/lo out -----
#define FA_STRIDE 68
#define FA_SMEM (3*64*FA_STRIDE*4)   // Ks, Vs, Ps

__global__ void __launch_bounds__(256)
flash_k(const float* __restrict__ qh, const float* __restrict__ kh,
        const float* __restrict__ vh,
        __nv_bfloat16* __restrict__ yh, __nv_bfloat16* __restrict__ yl) {
    extern __shared__ float fs[];
    float* Ks = fs;
    float* Vs = fs + 64*FA_STRIDE;
    float* Ps = fs + 2*64*FA_STRIDE;
    const int qt = blockIdx.x, bh = blockIdx.y;
    const int tid = threadIdx.x;
    const int r = tid >> 2, g = tid & 3;
    const int q0 = qt * 64;

    const float* Qg = qh + ((size_t)bh*T_ + q0) * 64;
    #pragma unroll
    for (int i = 0; i < 4; i++) {
        int j = tid + i*256;
        int row = j >> 4, c4 = (j & 15) * 4;
        *(float4*)&Ps[row*FA_STRIDE + c4] = *(const float4*)(Qg + row*64 + c4);
    }
    __syncthreads();
    float Qr[64];
    #pragma unroll
    for (int d4 = 0; d4 < 16; d4++) {
        float4 t = *(const float4*)&Ps[r*FA_STRIDE + d4*4];
        Qr[d4*4+0] = t.x; Qr[d4*4+1] = t.y; Qr[d4*4+2] = t.z; Qr[d4*4+3] = t.w;
    }

    float m = -1e30f, l = 0.f, O[16];
    #pragma unroll
    for (int i = 0; i < 16; i++) O[i] = 0.f;

    for (int kt = 0; kt <= qt; kt++) {
        __syncthreads();
        const float* Kg = kh + ((size_t)bh*T_ + kt*64) * 64;
        const float* Vg = vh + ((size_t)bh*T_ + kt*64) * 64;
        #pragma unroll
        for (int i = 0; i < 4; i++) {
            int j = tid + i*256;
            int row = j >> 4, c4 = (j & 15) * 4;
            *(float4*)&Ks[row*FA_STRIDE + c4] = *(const float4*)(Kg + row*64 + c4);
            *(float4*)&Vs[row*FA_STRIDE + c4] = *(const float4*)(Vg + row*64 + c4);
        }
        __syncthreads();

        float s[16];
        #pragma unroll
        for (int jj = 0; jj < 16; jj++) {
            int j = jj*4 + g;
            const float* kr = &Ks[j*FA_STRIDE];
            float a = 0.f;
            #pragma unroll
            for (int d4 = 0; d4 < 16; d4++) {
                float4 kv = *(const float4*)(kr + d4*4);
                a = fmaf(Qr[4*d4+0], kv.x, a);
                a = fmaf(Qr[4*d4+1], kv.y, a);
                a = fmaf(Qr[4*d4+2], kv.z, a);
                a = fmaf(Qr[4*d4+3], kv.w, a);
            }
            a *= 0.125f;
            if (kt == qt && j > r) a = -1e30f;
            s[jj] = a;
        }
        float tm = s[0];
        #pragma unroll
        for (int jj = 1; jj < 16; jj++) tm = fmaxf(tm, s[jj]);
        tm = fmaxf(tm, __shfl_xor_sync(0xffffffffu, tm, 1));
        tm = fmaxf(tm, __shfl_xor_sync(0xffffffffu, tm, 2));
        float nm = fmaxf(m, tm);
        float alpha = __expf(m - nm);
        float ls = 0.f;
        #pragma unroll
        for (int jj = 0; jj < 16; jj++) {
            float p = __expf(s[jj] - nm);
            Ps[r*FA_STRIDE + jj*4 + g] = p;
            ls += p;
        }
        ls += __shfl_xor_sync(0xffffffffu, ls, 1);
        ls += __shfl_xor_sync(0xffffffffu, ls, 2);
        l = l * alpha + ls;
        m = nm;
        #pragma unroll
        for (int i = 0; i < 16; i++) O[i] *= alpha;
        __syncthreads();
        #pragma unroll 4
        for (int j = 0; j < 64; j++) {
            float p = Ps[r*FA_STRIDE + j];
            const float* vr = &Vs[j*FA_STRIDE + g*16];
            #pragma unroll
            for (int d4 = 0; d4 < 4; d4++) {
                float4 vv = *(const float4*)(vr + d4*4);
                O[d4*4+0] = fmaf(p, vv.x, O[d4*4+0]);
                O[d4*4+1] = fmaf(p, vv.y, O[d4*4+1]);
                O[d4*4+2] = fmaf(p, vv.z, O[d4*4+2]);
                O[d4*4+3] = fmaf(p, vv.w, O[d4*4+3]);
            }
        }
    }

    const float inv = 1.f / l;
    const int b = bh / H_, h = bh % H_;
    size_t base = ((size_t)(b*T_ + q0 + r)) * E_ + h*64 + g*16;
    #pragma unroll
    for (int d2 = 0; d2 < 8; d2++) {
        float o0 = O[d2*2]*inv, o1 = O[d2*2+1]*inv;
        __nv_bfloat16 h0, l0, h1, l1;
        split_bf(o0, h0, l0); split_bf(o1, h1, l1);
        __nv_bfloat162 hv; hv.x = h0; hv.y = h1;
        __nv_bfloat162 lv; lv.x = l0; lv.y = l1;
        *(__nv_bfloat162*)(yh + base + d2*2) = hv;
        *(__nv_bfloat162*)(yl + base + d2*2) = lv;
    }
}

// ---------------- weight transpose+split: W[K,N] fp32 -> WT hi/lo [N,K] bf16 -
__global__ void transpose_split_k(const float* __restrict__ W,
                                  __nv_bfloat16* __restrict__ WTh,
                                  __nv_bfloat16* __restrict__ WTl,
                                  int K, int N) {
    __shared__ float t[32][33];
    const size_t lstride = (size_t)K * N;
    const float* Wl = W + lstride * blockIdx.z;
    __nv_bfloat16* Hh = WTh + lstride * blockIdx.z;
    __nv_bfloat16* Hl = WTl + lstride * blockIdx.z;
    int n0 = blockIdx.x * 32, k0 = blockIdx.y * 32;
    int x = threadIdx.x, y = threadIdx.y;   // 32 x 8
    #pragma unroll
    for (int i = 0; i < 32; i += 8)
        t[y + i][x] = Wl[(size_t)(k0 + y + i) * N + n0 + x];
    __syncthreads();
    #pragma unroll
    for (int i = 0; i < 32; i += 8) {
        float v = t[x][y + i];
        __nv_bfloat16 h, l; split_bf(v, h, l);
        Hh[(size_t)(n0 + y + i) * K + k0 + x] = h;
        Hl[(size_t)(n0 + y + i) * K + k0 + x] = l;
    }
}

// ---------------- wte pad+split: [V,E] fp32 -> [VP,E] bf16 hi/lo --------------
__global__ void wte_split_k(const float* __restrict__ wte,
                            __nv_bfloat16* __restrict__ wh,
                            __nv_bfloat16* __restrict__ wl) {
    int i = blockIdx.x * blockDim.x + threadIdx.x;
    if (i >= VP_*E_) return;
    int row = i / E_;
    float v = (row < V_) ? wte[i] : 0.f;
    __nv_bfloat16 h, l; split_bf(v, h, l);
    wh[i] = h; wl[i] = l;
}

// ---------------- embedding ----------------
__global__ void embed_k(const int* __restrict__ idx, const float* __restrict__ wte,
                        const float* __restrict__ wpe, float* __restrict__ x) {
    int i = blockIdx.x * blockDim.x + threadIdx.x;
    if (i >= M_*E_) return;
    int row = i / E_, e = i % E_;
    int t = row & (T_-1);
    x[i] = wte[(size_t)idx[row]*E_ + e] + wpe[t*E_ + e];
}

// ---------------- layernorm -> bf16 hi/lo (1 block / row) --------------------
__global__ void ln_k(const float* __restrict__ x, const float* __restrict__ g,
                     const float* __restrict__ b,
                     __nv_bfloat16* __restrict__ oh, __nv_bfloat16* __restrict__ ol) {
    int row = blockIdx.x;
    int tid = threadIdx.x;
    const float* xr = x + (size_t)row*E_;
    __shared__ float s1[256], s2[256];
    float a = 0.f, q = 0.f;
    for (int e = tid; e < E_; e += 256) { float v = xr[e]; a += v; q += v*v; }
    s1[tid] = a; s2[tid] = q; __syncthreads();
    for (int off = 128; off > 0; off >>= 1) {
        if (tid < off) { s1[tid] += s1[tid+off]; s2[tid] += s2[tid+off]; }
        __syncthreads();
    }
    float mu  = s1[0] * (1.f/E_);
    float var = s2[0] * (1.f/E_) - mu*mu;
    float inv = rsqrtf(var + 1e-5f);
    for (int e = tid; e < E_; e += 256) {
        float v = (xr[e] - mu) * inv * g[e] + b[e];
        __nv_bfloat16 h, l; split_bf(v, h, l);
        oh[(size_t)row*E_ + e] = h;
        ol[(size_t)row*E_ + e] = l;
    }
}

// ---------------- launch ----------------
extern "C" void kernel_launch(void* const* d_in, const int* in_sizes, int n_in,
                              void* d_out, int out_size) {
    const int*   idx    = (const int*)  d_in[0];
    const float* wte    = (const float*)d_in[1];
    const float* wpe    = (const float*)d_in[2];
    const float* ln1_g  = (const float*)d_in[3];
    const float* ln1_b  = (const float*)d_in[4];
    const float* attn_w = (const float*)d_in[5];
    const float* attn_b = (const float*)d_in[6];
    const float* proj_w = (const float*)d_in[7];
    const float* proj_b = (const float*)d_in[8];
    const float* ln2_g  = (const float*)d_in[9];
    const float* ln2_b  = (const float*)d_in[10];
    const float* fc_w   = (const float*)d_in[11];
    const float* fc_b   = (const float*)d_in[12];
    const float* fcp_w  = (const float*)d_in[13];
    const float* fcp_b  = (const float*)d_in[14];
    const float* lnf_g  = (const float*)d_in[15];
    const float* lnf_b  = (const float*)d_in[16];
    float* out = (float*)d_out;

    float *x, *qkvh;
    __nv_bfloat16 *xh, *xl, *yh, *yl, *h4h, *h4l;
    __nv_bfloat16 *attnTh, *attnTl, *projTh, *projTl, *fcTh, *fcTl, *fcpTh, *fcpTl;
    __nv_bfloat16 *wteh, *wtel;
    cudaGetSymbolAddress((void**)&x,    g_x);
    cudaGetSymbolAddress((void**)&qkvh, g_qkvh);
    cudaGetSymbolAddress((void**)&xh,   g_xh);   cudaGetSymbolAddress((void**)&xl,  g_xl);
    cudaGetSymbolAddress((void**)&yh,   g_yh);   cudaGetSymbolAddress((void**)&yl,  g_yl);
    cudaGetSymbolAddress((void**)&h4h,  g_h4h);  cudaGetSymbolAddress((void**)&h4l, g_h4l);
    cudaGetSymbolAddress((void**)&attnTh, g_attnTh); cudaGetSymbolAddress((void**)&attnTl, g_attnTl);
    cudaGetSymbolAddress((void**)&projTh, g_projTh); cudaGetSymbolAddress((void**)&projTl, g_projTl);
    cudaGetSymbolAddress((void**)&fcTh,   g_fcTh);   cudaGetSymbolAddress((void**)&fcTl,   g_fcTl);
    cudaGetSymbolAddress((void**)&fcpTh,  g_fcpTh);  cudaGetSymbolAddress((void**)&fcpTl,  g_fcpTl);
    cudaGetSymbolAddress((void**)&wteh,   g_wteh);   cudaGetSymbolAddress((void**)&wtel,   g_wtel);

    cudaFuncSetAttribute(gemm_bf<1,2>, cudaFuncAttributeMaxDynamicSharedMemorySize, GEMM_SMEM);
    cudaFuncSetAttribute(gemm_bf<3,0>, cudaFuncAttributeMaxDynamicSharedMemorySize, GEMM_SMEM);
    cudaFuncSetAttribute(gemm_bf<2,1>, cudaFuncAttributeMaxDynamicSharedMemorySize, GEMM_SMEM);
    cudaFuncSetAttribute(gemm_bf<0,0>, cudaFuncAttributeMaxDynamicSharedMemorySize, GEMM_SMEM);
    cudaFuncSetAttribute(flash_k,      cudaFuncAttributeMaxDynamicSharedMemorySize, FA_SMEM);

    // one-time weight prep
    dim3 tb(32, 8);
    transpose_split_k<<<dim3(3*E_/32, E_/32, L_), tb>>>(attn_w, attnTh, attnTl, E_, 3*E_);
    transpose_split_k<<<dim3(E_/32,   E_/32, L_), tb>>>(proj_w, projTh, projTl, E_, E_);
    transpose_split_k<<<dim3(4*E_/32, E_/32, L_), tb>>>(fc_w,   fcTh,   fcTl,   E_, 4*E_);
    transpose_split_k<<<dim3(E_/32, 4*E_/32, L_), tb>>>(fcp_w,  fcpTh,  fcpTl,  4*E_, E_);
    wte_split_k<<<(VP_*E_ + 255)/256, 256>>>(wte, wteh, wtel);

    embed_k<<<(M_*E_ + 255)/256, 256>>>(idx, wte, wpe, x);

    for (int l = 0; l < L_; l++) {
        ln_k<<<M_, 256>>>(x, ln1_g + l*E_, ln1_b + l*E_, xh, xl);
        gemm_bf<1,2><<<dim3(M_/128, 3*E_/128), 256, GEMM_SMEM>>>(
            xh, xl, attnTh + (size_t)l*3*E_*E_, attnTl + (size_t)l*3*E_*E_,
            attn_b + l*3*E_, nullptr, qkvh, nullptr, nullptr, M_, 3*E_, E_);
        flash_k<<<dim3(T_/64, B_*H_), 256, FA_SMEM>>>(
            qkvh, qkvh + BHTD_, qkvh + 2*BHTD_, yh, yl);
        gemm_bf<3,0><<<dim3(M_/128, E_/128), 256, GEMM_SMEM>>>(
            yh, yl, projTh + (size_t)l*E_*E_, projTl + (size_t)l*E_*E_,
            proj_b + l*E_, x, x, nullptr, nullptr, M_, E_, E_);
        ln_k<<<M_, 256>>>(x, ln2_g + l*E_, ln2_b + l*E_, xh, xl);
        gemm_bf<2,1><<<dim3(M_/128, 4*E_/128), 256, GEMM_SMEM>>>(
            xh, xl, fcTh + (size_t)l*4*E_*E_, fcTl + (size_t)l*4*E_*E_,
            fc_b + l*4*E_, nullptr, nullptr, h4h, h4l, M_, 4*E_, E_);
        gemm_bf<3,0><<<dim3(M_/128, E_/128), 256, GEMM_SMEM>>>(
            h4h, h4l, fcpTh + (size_t)l*4*E_*E_, fcpTl + (size_t)l*4*E_*E_,
            fcp_b + l*E_, x, x, nullptr, nullptr, M_, E_, 4*E_);
    }

    ln_k<<<M_, 256>>>(x, lnf_g, lnf_b, xh, xl);
    // logits = xln @ wte^T (padded rows are zero; stores guarded by N=V_)
    gemm_bf<0,0><<<dim3(M_/128, VP_/128), 256, GEMM_SMEM>>>(
        xh, xl, wteh, wtel, nullptr, nullptr, out, nullptr, nullptr, M_, V_, E_);
}

// round 6
// speedup vs baseline: 2.2231x; 1.0359x over previous
#include <cuda_runtime.h>
#include <cuda_bf16.h>
#include <math.h>
#include <stdint.h>

#define E_ 768
#define L_ 12
#define H_ 12
#define D_ 64
#define B_ 2
#define T_ 1024
#define V_ 50257
#define VP_ 50304            // padded to multiple of 128
#define M_ (B_*T_)           // 2048 rows
#define BHTD_ (B_*H_*T_*D_)  // 1572864

// ---------------- scratch (static device globals; no allocs) ----------------
__device__ float g_x   [M_*E_];             // residual stream (fp32)
__device__ float g_qkvh[3*BHTD_];           // q | k | v in [B,H,T,D]
// bf16 hi/lo activations
__device__ __nv_bfloat16 g_xh [M_*E_],  g_xl [M_*E_];     // LN outputs
__device__ __nv_bfloat16 g_yh [M_*E_],  g_yl [M_*E_];     // attention out
__device__ __nv_bfloat16 g_h4h[M_*4*E_],g_h4l[M_*4*E_];   // gelu out
// bf16 hi/lo transposed weights: [N,K] K-major
__device__ __nv_bfloat16 g_attnTh[L_*3*E_*E_], g_attnTl[L_*3*E_*E_];
__device__ __nv_bfloat16 g_projTh[L_*E_*E_],   g_projTl[L_*E_*E_];
__device__ __nv_bfloat16 g_fcTh  [L_*4*E_*E_], g_fcTl  [L_*4*E_*E_];
__device__ __nv_bfloat16 g_fcpTh [L_*4*E_*E_], g_fcpTl [L_*4*E_*E_];
__device__ __nv_bfloat16 g_wteh  [VP_*E_],     g_wtel  [VP_*E_];

// ---------------- helpers ----------------
__device__ __forceinline__ uint32_t cvta_smem(const void* p){
    uint32_t a;
    asm("{.reg .u64 t; cvta.to.shared.u64 t, %1; cvt.u32.u64 %0, t;}" : "=r"(a) : "l"(p));
    return a;
}
__device__ __forceinline__ void ldsm4(uint32_t* r, uint32_t addr){
    asm volatile("ldmatrix.sync.aligned.m8n8.x4.shared.b16 {%0,%1,%2,%3}, [%4];"
        : "=r"(r[0]),"=r"(r[1]),"=r"(r[2]),"=r"(r[3]) : "r"(addr));
}
__device__ __forceinline__ void mma16816(float* d, const uint32_t* a, const uint32_t* b){
    asm volatile("mma.sync.aligned.m16n8k16.row.col.f32.bf16.bf16.f32 "
        "{%0,%1,%2,%3}, {%4,%5,%6,%7}, {%8,%9}, {%0,%1,%2,%3};"
        : "+f"(d[0]),"+f"(d[1]),"+f"(d[2]),"+f"(d[3])
        : "r"(a[0]),"r"(a[1]),"r"(a[2]),"r"(a[3]), "r"(b[0]),"r"(b[1]));
}
__device__ __forceinline__ void cpa16(uint32_t s, const void* g){
    asm volatile("cp.async.cg.shared.global [%0], [%1], 16;" :: "r"(s), "l"(g));
}
__device__ __forceinline__ float gelu_f(float v){
    return 0.5f * v * (1.0f + erff(v * 0.70710678118654752f));
}
__device__ __forceinline__ void split_bf(float v, __nv_bfloat16& h, __nv_bfloat16& l){
    h = __float2bfloat16_rn(v);
    l = __float2bfloat16_rn(v - __bfloat162float(h));
}

// ---------------- bf16-split mma.sync GEMM: 128x128x32, cp.async 2-stage -----
#define ROWB 80                 // smem row stride (bytes): 64B data + 16B pad
#define BUF_AH 0
#define BUF_AL 10240
#define BUF_BH 20480
#define BUF_BL 30720
#define STAGEB 40960
#define NS 2
#define GEMM_SMEM (NS*STAGEB)   // 81920 -> 2 CTAs per SM

// EPI: 0 none, 1 +bias, 2 gelu(+bias), 3 +bias+residual
// OUT: 0 fp32 C, 1 bf16 hi/lo (Ch,Cl), 2 qkv head-scatter into C (q|k|v)
template<int EPI, int OUT>
__global__ void __launch_bounds__(256, 2)
gemm_bf(const __nv_bfloat16* __restrict__ Ahg, const __nv_bfloat16* __restrict__ Alg,
        const __nv_bfloat16* __restrict__ Bhg, const __nv_bfloat16* __restrict__ Blg,
        const float* __restrict__ bias, const float* __restrict__ res,
        float* __restrict__ C, __nv_bfloat16* __restrict__ Ch,
        __nv_bfloat16* __restrict__ Cl, int M, int N, int K) {
    extern __shared__ char smraw[];
    const uint32_t sb = cvta_smem(smraw);
    const int tid = threadIdx.x;
    const int lane = tid & 31, wid = tid >> 5;
    const int wm = wid & 3, wn = wid >> 2;            // 4 x 2 warp grid
    const int m0 = blockIdx.x * 128, n0 = blockIdx.y * 128;
    const int nkb = K >> 5;

    float acc[2][8][4];
    #pragma unroll
    for (int i = 0; i < 2; i++)
        #pragma unroll
        for (int j = 0; j < 8; j++)
            #pragma unroll
            for (int t = 0; t < 4; t++) acc[i][j][t] = 0.f;

    // loader: 512 16B-chunks per tile / 256 threads = 2 per thread per tile
    const int r0 = tid >> 2,         c0 = tid & 3;
    const int r1 = (tid+256) >> 2,   c1 = (tid+256) & 3;
    const uint32_t so0 = (uint32_t)(r0*ROWB + c0*16);
    const uint32_t so1 = (uint32_t)(r1*ROWB + c1*16);

    auto load_stage = [&](int kb){
        const uint32_t st = sb + (uint32_t)(kb & 1) * STAGEB;
        const int k0 = kb * 32;
        const size_t a0 = (size_t)(m0+r0)*K + k0 + c0*8;
        const size_t a1 = (size_t)(m0+r1)*K + k0 + c1*8;
        const size_t b0 = (size_t)(n0+r0)*K + k0 + c0*8;
        const size_t b1 = (size_t)(n0+r1)*K + k0 + c1*8;
        cpa16(st+BUF_AH+so0, Ahg+a0);  cpa16(st+BUF_AH+so1, Ahg+a1);
        cpa16(st+BUF_AL+so0, Alg+a0);  cpa16(st+BUF_AL+so1, Alg+a1);
        cpa16(st+BUF_BH+so0, Bhg+b0);  cpa16(st+BUF_BH+so1, Bhg+b1);
        cpa16(st+BUF_BL+so0, Blg+b0);  cpa16(st+BUF_BL+so1, Blg+b1);
    };

    load_stage(0);
    asm volatile("cp.async.commit_group;" ::: "memory");
    load_stage(1);
    asm volatile("cp.async.commit_group;" ::: "memory");

    for (int kb = 0; kb < nkb; kb++) {
        asm volatile("cp.async.wait_group 1;" ::: "memory");
        __syncthreads();

        const uint32_t st = sb + (uint32_t)(kb & 1) * STAGEB;
        #pragma unroll
        for (int ks = 0; ks < 2; ks++) {
            uint32_t ah[2][4], al[2][4], bhf[8][2], blf[8][2];
            #pragma unroll
            for (int mi = 0; mi < 2; mi++) {
                int row = wm*32 + mi*16 + (lane & 15);
                int ch  = 2*ks + (lane >> 4);
                uint32_t off = (uint32_t)(row*ROWB + ch*16);
                ldsm4(ah[mi], st + BUF_AH + off);
                ldsm4(al[mi], st + BUF_AL + off);
            }
            #pragma unroll
            for (int p2 = 0; p2 < 4; p2++) {
                int nr = wn*64 + p2*16 + (lane & 7) + ((lane >> 4) << 3);
                int ch = 2*ks + ((lane >> 3) & 1);
                uint32_t off = (uint32_t)(nr*ROWB + ch*16);
                uint32_t t[4];
                ldsm4(t, st + BUF_BH + off);
                bhf[2*p2][0]=t[0]; bhf[2*p2][1]=t[1]; bhf[2*p2+1][0]=t[2]; bhf[2*p2+1][1]=t[3];
                ldsm4(t, st + BUF_BL + off);
                blf[2*p2][0]=t[0]; blf[2*p2][1]=t[1]; blf[2*p2+1][0]=t[2]; blf[2*p2+1][1]=t[3];
            }
            #pragma unroll
            for (int mi = 0; mi < 2; mi++)
                #pragma unroll
                for (int nj = 0; nj < 8; nj++) {
                    mma16816(acc[mi][nj], ah[mi], bhf[nj]);
                    mma16816(acc[mi][nj], ah[mi], blf[nj]);
                    mma16816(acc[mi][nj], al[mi], bhf[nj]);
                }
        }
        // buffer (kb&1) is now fully consumed by ALL warps; safe to refill
        __syncthreads();
        if (kb + 2 < nkb) load_stage(kb + 2);
        asm volatile("cp.async.commit_group;" ::: "memory");
    }

    // ---- epilogue ----
    const int mrow = m0 + wm*32 + (lane >> 2);
    const int ncol = n0 + wn*64 + 2*(lane & 3);
    const bool vec_ok = ((N & 1) == 0);
    #pragma unroll
    for (int mi = 0; mi < 2; mi++) {
        #pragma unroll
        for (int nj = 0; nj < 8; nj++) {
            int c = ncol + nj*8;
            #pragma unroll
            for (int h2 = 0; h2 < 2; h2++) {
                int rr = mrow + mi*16 + h2*8;
                float v0 = acc[mi][nj][h2*2], v1 = acc[mi][nj][h2*2+1];
                if (EPI >= 1 && c < N)     v0 += bias[c];
                if (EPI >= 1 && c+1 < N)   v1 += bias[c+1];
                if (EPI == 2) { v0 = gelu_f(v0); v1 = gelu_f(v1); }
                if (OUT == 2) {
                    // qkv scatter: C = base of q|k|v, each [B,H,T,D]
                    int which = c / E_, e = c % E_;
                    int hh = e >> 6, d = e & 63;
                    int b = rr >> 10, t = rr & (T_-1);
                    float2 o; o.x = v0; o.y = v1;
                    *(float2*)(C + (size_t)which*BHTD_ +
                               (((size_t)(b*H_ + hh)*T_) + t)*D_ + d) = o;
                } else if (OUT == 1) {
                    if (EPI == 3) {
                        v0 += res[(size_t)rr*N + c]; v1 += res[(size_t)rr*N + c + 1];
                    }
                    __nv_bfloat16 h0, l0, h1, l1;
                    split_bf(v0, h0, l0); split_bf(v1, h1, l1);
                    __nv_bfloat162 hv; hv.x = h0; hv.y = h1;
                    __nv_bfloat162 lv; lv.x = l0; lv.y = l1;
                    *(__nv_bfloat162*)(Ch + (size_t)rr*N + c) = hv;
                    *(__nv_bfloat162*)(Cl + (size_t)rr*N + c) = lv;
                } else {
                    if (vec_ok && c + 1 < N) {
                        if (EPI == 3) {
                            v0 += res[(size_t)rr*N + c]; v1 += res[(size_t)rr*N + c + 1];
                        }
                        float2 o; o.x = v0; o.y = v1;
                        *(float2*)(C + (size_t)rr*N + c) = o;
                    } else {
                        if (c < N) {
                            if (EPI == 3) v0 += res[(size_t)rr*N + c];
                            C[(size_t)rr*N + c] = v0;
                        }
                        if (c + 1 < N) {
                            if (EPI == 3) v1 += res[(size_t)rr*N + c + 1];
                            C[(size_t)rr*N + c + 1] = v1;
                        }
                    }
                }
            }
        }
    }
}

// ---------------- flash attention: 64q x 64k tiles, fp32, bf16 hi/lo out -----
#define FA_STRIDE 68
#define FA_SMEM (3*64*FA_STRIDE*4)   // Ks, Vs, Ps

__global__ void __launch_bounds__(256)
flash_k(const float* __restrict__ qh, const float* __restrict__ kh,
        const float* __restrict__ vh,
        __nv_bfloat16* __restrict__ yh, __nv_bfloat16* __restrict__ yl) {
    extern __shared__ float fs[];
    float* Ks = fs;
    float* Vs = fs + 64*FA_STRIDE;
    float* Ps = fs + 2*64*FA_STRIDE;
    const int qt = blockIdx.x, bh = blockIdx.y;
    const int tid = threadIdx.x;
    const int r = tid >> 2, g = tid & 3;
    const int q0 = qt * 64;

    const float* Qg = qh + ((size_t)bh*T_ + q0) * 64;
    #pragma unroll
    for (int i = 0; i < 4; i++) {
        int j = tid + i*256;
        int row = j >> 4, c4 = (j & 15) * 4;
        *(float4*)&Ps[row*FA_STRIDE + c4] = *(const float4*)(Qg + row*64 + c4);
    }
    __syncthreads();
    float Qr[64];
    #pragma unroll
    for (int d4 = 0; d4 < 16; d4++) {
        float4 t = *(const float4*)&Ps[r*FA_STRIDE + d4*4];
        Qr[d4*4+0] = t.x; Qr[d4*4+1] = t.y; Qr[d4*4+2] = t.z; Qr[d4*4+3] = t.w;
    }

    float m = -1e30f, l = 0.f, O[16];
    #pragma unroll
    for (int i = 0; i < 16; i++) O[i] = 0.f;

    for (int kt = 0; kt <= qt; kt++) {
        __syncthreads();
        const float* Kg = kh + ((size_t)bh*T_ + kt*64) * 64;
        const float* Vg = vh + ((size_t)bh*T_ + kt*64) * 64;
        #pragma unroll
        for (int i = 0; i < 4; i++) {
            int j = tid + i*256;
            int row = j >> 4, c4 = (j & 15) * 4;
            *(float4*)&Ks[row*FA_STRIDE + c4] = *(const float4*)(Kg + row*64 + c4);
            *(float4*)&Vs[row*FA_STRIDE + c4] = *(const float4*)(Vg + row*64 + c4);
        }
        __syncthreads();

        float s[16];
        #pragma unroll
        for (int jj = 0; jj < 16; jj++) {
            int j = jj*4 + g;
            const float* kr = &Ks[j*FA_STRIDE];
            float a = 0.f;
            #pragma unroll
            for (int d4 = 0; d4 < 16; d4++) {
                float4 kv = *(const float4*)(kr + d4*4);
                a = fmaf(Qr[4*d4+0], kv.x, a);
                a = fmaf(Qr[4*d4+1], kv.y, a);
                a = fmaf(Qr[4*d4+2], kv.z, a);
                a = fmaf(Qr[4*d4+3], kv.w, a);
            }
            a *= 0.125f;
            if (kt == qt && j > r) a = -1e30f;
            s[jj] = a;
        }
        float tm = s[0];
        #pragma unroll
        for (int jj = 1; jj < 16; jj++) tm = fmaxf(tm, s[jj]);
        tm = fmaxf(tm, __shfl_xor_sync(0xffffffffu, tm, 1));
        tm = fmaxf(tm, __shfl_xor_sync(0xffffffffu, tm, 2));
        float nm = fmaxf(m, tm);
        float alpha = __expf(m - nm);
        float ls = 0.f;
        #pragma unroll
        for (int jj = 0; jj < 16; jj++) {
            float p = __expf(s[jj] - nm);
            Ps[r*FA_STRIDE + jj*4 + g] = p;
            ls += p;
        }
        ls += __shfl_xor_sync(0xffffffffu, ls, 1);
        ls += __shfl_xor_sync(0xffffffffu, ls, 2);
        l = l * alpha + ls;
        m = nm;
        #pragma unroll
        for (int i = 0; i < 16; i++) O[i] *= alpha;
        __syncthreads();
        #pragma unroll 4
        for (int j = 0; j < 64; j++) {
            float p = Ps[r*FA_STRIDE + j];
            const float* vr = &Vs[j*FA_STRIDE + g*16];
            #pragma unroll
            for (int d4 = 0; d4 < 4; d4++) {
                float4 vv = *(const float4*)(vr + d4*4);
                O[d4*4+0] = fmaf(p, vv.x, O[d4*4+0]);
                O[d4*4+1] = fmaf(p, vv.y, O[d4*4+1]);
                O[d4*4+2] = fmaf(p, vv.z, O[d4*4+2]);
                O[d4*4+3] = fmaf(p, vv.w, O[d4*4+3]);
            }
        }
    }

    const float inv = 1.f / l;
    const int b = bh / H_, h = bh % H_;
    size_t base = ((size_t)(b*T_ + q0 + r)) * E_ + h*64 + g*16;
    #pragma unroll
    for (int d2 = 0; d2 < 8; d2++) {
        float o0 = O[d2*2]*inv, o1 = O[d2*2+1]*inv;
        __nv_bfloat16 h0, l0, h1, l1;
        split_bf(o0, h0, l0); split_bf(o1, h1, l1);
        __nv_bfloat162 hv; hv.x = h0; hv.y = h1;
        __nv_bfloat162 lv; lv.x = l0; lv.y = l1;
        *(__nv_bfloat162*)(yh + base + d2*2) = hv;
        *(__nv_bfloat162*)(yl + base + d2*2) = lv;
    }
}

// ---------------- weight transpose+split: W[K,N] fp32 -> WT hi/lo [N,K] bf16 -
__global__ void transpose_split_k(const float* __restrict__ W,
                                  __nv_bfloat16* __restrict__ WTh,
                                  __nv_bfloat16* __restrict__ WTl,
                                  int K, int N) {
    __shared__ float t[32][33];
    const size_t lstride = (size_t)K * N;
    const float* Wl = W + lstride * blockIdx.z;
    __nv_bfloat16* Hh = WTh + lstride * blockIdx.z;
    __nv_bfloat16* Hl = WTl + lstride * blockIdx.z;
    int n0 = blockIdx.x * 32, k0 = blockIdx.y * 32;
    int x = threadIdx.x, y = threadIdx.y;   // 32 x 8
    #pragma unroll
    for (int i = 0; i < 32; i += 8)
        t[y + i][x] = Wl[(size_t)(k0 + y + i) * N + n0 + x];
    __syncthreads();
    #pragma unroll
    for (int i = 0; i < 32; i += 8) {
        float v = t[x][y + i];
        __nv_bfloat16 h, l; split_bf(v, h, l);
        Hh[(size_t)(n0 + y + i) * K + k0 + x] = h;
        Hl[(size_t)(n0 + y + i) * K + k0 + x] = l;
    }
}

// ---------------- wte pad+split: [V,E] fp32 -> [VP,E] bf16 hi/lo --------------
__global__ void wte_split_k(const float* __restrict__ wte,
                            __nv_bfloat16* __restrict__ wh,
                            __nv_bfloat16* __restrict__ wl) {
    int i = blockIdx.x * blockDim.x + threadIdx.x;
    if (i >= VP_*E_) return;
    int row = i / E_;
    float v = (row < V_) ? wte[i] : 0.f;
    __nv_bfloat16 h, l; split_bf(v, h, l);
    wh[i] = h; wl[i] = l;
}

// ---------------- embedding ----------------
__global__ void embed_k(const int* __restrict__ idx, const float* __restrict__ wte,
                        const float* __restrict__ wpe, float* __restrict__ x) {
    int i = blockIdx.x * blockDim.x + threadIdx.x;
    if (i >= M_*E_) return;
    int row = i / E_, e = i % E_;
    int t = row & (T_-1);
    x[i] = wte[(size_t)idx[row]*E_ + e] + wpe[t*E_ + e];
}

// ---------------- layernorm -> bf16 hi/lo (1 block / row) --------------------
__global__ void ln_k(const float* __restrict__ x, const float* __restrict__ g,
                     const float* __restrict__ b,
                     __nv_bfloat16* __restrict__ oh, __nv_bfloat16* __restrict__ ol) {
    int row = blockIdx.x;
    int tid = threadIdx.x;
    const float* xr = x + (size_t)row*E_;
    __shared__ float s1[256], s2[256];
    float a = 0.f, q = 0.f;
    for (int e = tid; e < E_; e += 256) { float v = xr[e]; a += v; q += v*v; }
    s1[tid] = a; s2[tid] = q; __syncthreads();
    for (int off = 128; off > 0; off >>= 1) {
        if (tid < off) { s1[tid] += s1[tid+off]; s2[tid] += s2[tid+off]; }
        __syncthreads();
    }
    float mu  = s1[0] * (1.f/E_);
    float var = s2[0] * (1.f/E_) - mu*mu;
    float inv = rsqrtf(var + 1e-5f);
    for (int e = tid; e < E_; e += 256) {
        float v = (xr[e] - mu) * inv * g[e] + b[e];
        __nv_bfloat16 h, l; split_bf(v, h, l);
        oh[(size_t)row*E_ + e] = h;
        ol[(size_t)row*E_ + e] = l;
    }
}

// ---------------- launch ----------------
extern "C" void kernel_launch(void* const* d_in, const int* in_sizes, int n_in,
                              void* d_out, int out_size) {
    const int*   idx    = (const int*)  d_in[0];
    const float* wte    = (const float*)d_in[1];
    const float* wpe    = (const float*)d_in[2];
    const float* ln1_g  = (const float*)d_in[3];
    const float* ln1_b  = (const float*)d_in[4];
    const float* attn_w = (const float*)d_in[5];
    const float* attn_b = (const float*)d_in[6];
    const float* proj_w = (const float*)d_in[7];
    const float* proj_b = (const float*)d_in[8];
    const float* ln2_g  = (const float*)d_in[9];
    const float* ln2_b  = (const float*)d_in[10];
    const float* fc_w   = (const float*)d_in[11];
    const float* fc_b   = (const float*)d_in[12];
    const float* fcp_w  = (const float*)d_in[13];
    const float* fcp_b  = (const float*)d_in[14];
    const float* lnf_g  = (const float*)d_in[15];
    const float* lnf_b  = (const float*)d_in[16];
    float* out = (float*)d_out;

    float *x, *qkvh;
    __nv_bfloat16 *xh, *xl, *yh, *yl, *h4h, *h4l;
    __nv_bfloat16 *attnTh, *attnTl, *projTh, *projTl, *fcTh, *fcTl, *fcpTh, *fcpTl;
    __nv_bfloat16 *wteh, *wtel;
    cudaGetSymbolAddress((void**)&x,    g_x);
    cudaGetSymbolAddress((void**)&qkvh, g_qkvh);
    cudaGetSymbolAddress((void**)&xh,   g_xh);   cudaGetSymbolAddress((void**)&xl,  g_xl);
    cudaGetSymbolAddress((void**)&yh,   g_yh);   cudaGetSymbolAddress((void**)&yl,  g_yl);
    cudaGetSymbolAddress((void**)&h4h,  g_h4h);  cudaGetSymbolAddress((void**)&h4l, g_h4l);
    cudaGetSymbolAddress((void**)&attnTh, g_attnTh); cudaGetSymbolAddress((void**)&attnTl, g_attnTl);
    cudaGetSymbolAddress((void**)&projTh, g_projTh); cudaGetSymbolAddress((void**)&projTl, g_projTl);
    cudaGetSymbolAddress((void**)&fcTh,   g_fcTh);   cudaGetSymbolAddress((void**)&fcTl,   g_fcTl);
    cudaGetSymbolAddress((void**)&fcpTh,  g_fcpTh);  cudaGetSymbolAddress((void**)&fcpTl,  g_fcpTl);
    cudaGetSymbolAddress((void**)&wteh,   g_wteh);   cudaGetSymbolAddress((void**)&wtel,   g_wtel);

    cudaFuncSetAttribute(gemm_bf<1,2>, cudaFuncAttributeMaxDynamicSharedMemorySize, GEMM_SMEM);
    cudaFuncSetAttribute(gemm_bf<3,0>, cudaFuncAttributeMaxDynamicSharedMemorySize, GEMM_SMEM);
    cudaFuncSetAttribute(gemm_bf<2,1>, cudaFuncAttributeMaxDynamicSharedMemorySize, GEMM_SMEM);
    cudaFuncSetAttribute(gemm_bf<0,0>, cudaFuncAttributeMaxDynamicSharedMemorySize, GEMM_SMEM);
    cudaFuncSetAttribute(flash_k,      cudaFuncAttributeMaxDynamicSharedMemorySize, FA_SMEM);

    // one-time weight prep
    dim3 tb(32, 8);
    transpose_split_k<<<dim3(3*E_/32, E_/32, L_), tb>>>(attn_w, attnTh, attnTl, E_, 3*E_);
    transpose_split_k<<<dim3(E_/32,   E_/32, L_), tb>>>(proj_w, projTh, projTl, E_, E_);
    transpose_split_k<<<dim3(4*E_/32, E_/32, L_), tb>>>(fc_w,   fcTh,   fcTl,   E_, 4*E_);
    transpose_split_k<<<dim3(E_/32, 4*E_/32, L_), tb>>>(fcp_w,  fcpTh,  fcpTl,  4*E_, E_);
    wte_split_k<<<(VP_*E_ + 255)/256, 256>>>(wte, wteh, wtel);

    embed_k<<<(M_*E_ + 255)/256, 256>>>(idx, wte, wpe, x);

    for (int l = 0; l < L_; l++) {
        ln_k<<<M_, 256>>>(x, ln1_g + l*E_, ln1_b + l*E_, xh, xl);
        gemm_bf<1,2><<<dim3(M_/128, 3*E_/128), 256, GEMM_SMEM>>>(
            xh, xl, attnTh + (size_t)l*3*E_*E_, attnTl + (size_t)l*3*E_*E_,
            attn_b + l*3*E_, nullptr, qkvh, nullptr, nullptr, M_, 3*E_, E_);
        flash_k<<<dim3(T_/64, B_*H_), 256, FA_SMEM>>>(
            qkvh, qkvh + BHTD_, qkvh + 2*BHTD_, yh, yl);
        gemm_bf<3,0><<<dim3(M_/128, E_/128), 256, GEMM_SMEM>>>(
            yh, yl, projTh + (size_t)l*E_*E_, projTl + (size_t)l*E_*E_,
            proj_b + l*E_, x, x, nullptr, nullptr, M_, E_, E_);
        ln_k<<<M_, 256>>>(x, ln2_g + l*E_, ln2_b + l*E_, xh, xl);
        gemm_bf<2,1><<<dim3(M_/128, 4*E_/128), 256, GEMM_SMEM>>>(
            xh, xl, fcTh + (size_t)l*4*E_*E_, fcTl + (size_t)l*4*E_*E_,
            fc_b + l*4*E_, nullptr, nullptr, h4h, h4l, M_, 4*E_, E_);
        gemm_bf<3,0><<<dim3(M_/128, E_/128), 256, GEMM_SMEM>>>(
            h4h, h4l, fcpTh + (size_t)l*4*E_*E_, fcpTl + (size_t)l*4*E_*E_,
            fcp_b + l*E_, x, x, nullptr, nullptr, M_, E_, 4*E_);
    }

    ln_k<<<M_, 256>>>(x, lnf_g, lnf_b, xh, xl);
    // logits = xln @ wte^T (padded rows are zero; stores guarded by N=V_)
    gemm_bf<0,0><<<dim3(M_/128, VP_/128), 256, GEMM_SMEM>>>(
        xh, xl, wteh, wtel, nullptr, nullptr, out, nullptr, nullptr, M_, V_, E_);
}

// round 7
// speedup vs baseline: 3.6309x; 1.6332x over previous
#include <cuda_runtime.h>
#include <cuda_bf16.h>
#include <math.h>
#include <stdint.h>

#define E_ 768
#define L_ 12
#define H_ 12
#define D_ 64
#define B_ 2
#define T_ 1024
#define V_ 50257
#define VP_ 50304            // padded to multiple of 128
#define M_ (B_*T_)           // 2048 rows
#define BHTD_ (B_*H_*T_*D_)  // 1572864

// ---------------- scratch (static device globals; no allocs) ----------------
__device__ float g_x   [M_*E_];             // residual stream (fp32)
// q/k/v in bf16 hi/lo: order qh,ql,kh,kl,vh,vl, each [B,H,T,D]
__device__ __nv_bfloat16 g_qkv6[6*BHTD_];
// bf16 hi/lo activations
__device__ __nv_bfloat16 g_xh [M_*E_],  g_xl [M_*E_];     // LN outputs
__device__ __nv_bfloat16 g_yh [M_*E_],  g_yl [M_*E_];     // attention out
__device__ __nv_bfloat16 g_h4h[M_*4*E_],g_h4l[M_*4*E_];   // gelu out
// bf16 hi/lo transposed weights: [N,K] K-major
__device__ __nv_bfloat16 g_attnTh[L_*3*E_*E_], g_attnTl[L_*3*E_*E_];
__device__ __nv_bfloat16 g_projTh[L_*E_*E_],   g_projTl[L_*E_*E_];
__device__ __nv_bfloat16 g_fcTh  [L_*4*E_*E_], g_fcTl  [L_*4*E_*E_];
__device__ __nv_bfloat16 g_fcpTh [L_*4*E_*E_], g_fcpTl [L_*4*E_*E_];
__device__ __nv_bfloat16 g_wteh  [VP_*E_],     g_wtel  [VP_*E_];

// ---------------- helpers ----------------
__device__ __forceinline__ uint32_t cvta_smem(const void* p){
    uint32_t a;
    asm("{.reg .u64 t; cvta.to.shared.u64 t, %1; cvt.u32.u64 %0, t;}" : "=r"(a) : "l"(p));
    return a;
}
__device__ __forceinline__ void ldsm4(uint32_t* r, uint32_t addr){
    asm volatile("ldmatrix.sync.aligned.m8n8.x4.shared.b16 {%0,%1,%2,%3}, [%4];"
        : "=r"(r[0]),"=r"(r[1]),"=r"(r[2]),"=r"(r[3]) : "r"(addr));
}
__device__ __forceinline__ void ldsm4t(uint32_t* r, uint32_t addr){
    asm volatile("ldmatrix.sync.aligned.m8n8.x4.trans.shared.b16 {%0,%1,%2,%3}, [%4];"
        : "=r"(r[0]),"=r"(r[1]),"=r"(r[2]),"=r"(r[3]) : "r"(addr));
}
__device__ __forceinline__ void mma16816(float* d, const uint32_t* a, const uint32_t* b){
    asm volatile("mma.sync.aligned.m16n8k16.row.col.f32.bf16.bf16.f32 "
        "{%0,%1,%2,%3}, {%4,%5,%6,%7}, {%8,%9}, {%0,%1,%2,%3};"
        : "+f"(d[0]),"+f"(d[1]),"+f"(d[2]),"+f"(d[3])
        : "r"(a[0]),"r"(a[1]),"r"(a[2]),"r"(a[3]), "r"(b[0]),"r"(b[1]));
}
__device__ __forceinline__ void cpa16(uint32_t s, const void* g){
    asm volatile("cp.async.cg.shared.global [%0], [%1], 16;" :: "r"(s), "l"(g));
}
__device__ __forceinline__ float gelu_f(float v){
    return 0.5f * v * (1.0f + erff(v * 0.70710678118654752f));
}
__device__ __forceinline__ uint32_t packbf(float a, float b){
    __nv_bfloat162 t = __floats2bfloat162_rn(a, b);
    return *reinterpret_cast<uint32_t*>(&t);
}
__device__ __forceinline__ float bfhi(float a){
    return __bfloat162float(__float2bfloat16_rn(a));
}
__device__ __forceinline__ void split_bf(float v, __nv_bfloat16& h, __nv_bfloat16& l){
    h = __float2bfloat16_rn(v);
    l = __float2bfloat16_rn(v - __bfloat162float(h));
}

// ---------------- bf16-split mma.sync GEMM: 128x128x32, cp.async 2-stage -----
#define ROWB 80
#define BUF_AH 0
#define BUF_AL 10240
#define BUF_BH 20480
#define BUF_BL 30720
#define STAGEB 40960
#define GEMM_SMEM (2*STAGEB)    // 81920 -> 2 CTAs per SM

// EPI: 0 none, 1 +bias, 2 gelu(+bias), 3 +bias+residual
// OUT: 0 fp32 C, 1 bf16 hi/lo (Ch,Cl), 2 qkv hi/lo head-scatter into Ch (6 arrays)
template<int EPI, int OUT>
__global__ void __launch_bounds__(256, 2)
gemm_bf(const __nv_bfloat16* __restrict__ Ahg, const __nv_bfloat16* __restrict__ Alg,
        const __nv_bfloat16* __restrict__ Bhg, const __nv_bfloat16* __restrict__ Blg,
        const float* __restrict__ bias, const float* __restrict__ res,
        float* __restrict__ C, __nv_bfloat16* __restrict__ Ch,
        __nv_bfloat16* __restrict__ Cl, int M, int N, int K) {
    extern __shared__ char smraw[];
    const uint32_t sb = cvta_smem(smraw);
    const int tid = threadIdx.x;
    const int lane = tid & 31, wid = tid >> 5;
    const int wm = wid & 3, wn = wid >> 2;
    const int m0 = blockIdx.x * 128, n0 = blockIdx.y * 128;
    const int nkb = K >> 5;

    float acc[2][8][4];
    #pragma unroll
    for (int i = 0; i < 2; i++)
        #pragma unroll
        for (int j = 0; j < 8; j++)
            #pragma unroll
            for (int t = 0; t < 4; t++) acc[i][j][t] = 0.f;

    const int r0 = tid >> 2,         c0 = tid & 3;
    const int r1 = (tid+256) >> 2,   c1 = (tid+256) & 3;
    const uint32_t so0 = (uint32_t)(r0*ROWB + c0*16);
    const uint32_t so1 = (uint32_t)(r1*ROWB + c1*16);

    auto load_stage = [&](int kb){
        const uint32_t st = sb + (uint32_t)(kb & 1) * STAGEB;
        const int k0 = kb * 32;
        const size_t a0 = (size_t)(m0+r0)*K + k0 + c0*8;
        const size_t a1 = (size_t)(m0+r1)*K + k0 + c1*8;
        const size_t b0 = (size_t)(n0+r0)*K + k0 + c0*8;
        const size_t b1 = (size_t)(n0+r1)*K + k0 + c1*8;
        cpa16(st+BUF_AH+so0, Ahg+a0);  cpa16(st+BUF_AH+so1, Ahg+a1);
        cpa16(st+BUF_AL+so0, Alg+a0);  cpa16(st+BUF_AL+so1, Alg+a1);
        cpa16(st+BUF_BH+so0, Bhg+b0);  cpa16(st+BUF_BH+so1, Bhg+b1);
        cpa16(st+BUF_BL+so0, Blg+b0);  cpa16(st+BUF_BL+so1, Blg+b1);
    };

    load_stage(0);
    asm volatile("cp.async.commit_group;" ::: "memory");
    load_stage(1);
    asm volatile("cp.async.commit_group;" ::: "memory");

    for (int kb = 0; kb < nkb; kb++) {
        asm volatile("cp.async.wait_group 1;" ::: "memory");
        __syncthreads();

        const uint32_t st = sb + (uint32_t)(kb & 1) * STAGEB;
        #pragma unroll
        for (int ks = 0; ks < 2; ks++) {
            uint32_t ah[2][4], al[2][4], bhf[8][2], blf[8][2];
            #pragma unroll
            for (int mi = 0; mi < 2; mi++) {
                int row = wm*32 + mi*16 + (lane & 15);
                int ch  = 2*ks + (lane >> 4);
                uint32_t off = (uint32_t)(row*ROWB + ch*16);
                ldsm4(ah[mi], st + BUF_AH + off);
                ldsm4(al[mi], st + BUF_AL + off);
            }
            #pragma unroll
            for (int p2 = 0; p2 < 4; p2++) {
                int nr = wn*64 + p2*16 + (lane & 7) + ((lane >> 4) << 3);
                int ch = 2*ks + ((lane >> 3) & 1);
                uint32_t off = (uint32_t)(nr*ROWB + ch*16);
                uint32_t t[4];
                ldsm4(t, st + BUF_BH + off);
                bhf[2*p2][0]=t[0]; bhf[2*p2][1]=t[1]; bhf[2*p2+1][0]=t[2]; bhf[2*p2+1][1]=t[3];
                ldsm4(t, st + BUF_BL + off);
                blf[2*p2][0]=t[0]; blf[2*p2][1]=t[1]; blf[2*p2+1][0]=t[2]; blf[2*p2+1][1]=t[3];
            }
            #pragma unroll
            for (int mi = 0; mi < 2; mi++)
                #pragma unroll
                for (int nj = 0; nj < 8; nj++) {
                    mma16816(acc[mi][nj], ah[mi], bhf[nj]);
                    mma16816(acc[mi][nj], ah[mi], blf[nj]);
                    mma16816(acc[mi][nj], al[mi], bhf[nj]);
                }
        }
        __syncthreads();
        if (kb + 2 < nkb) load_stage(kb + 2);
        asm volatile("cp.async.commit_group;" ::: "memory");
    }

    // ---- epilogue ----
    const int mrow = m0 + wm*32 + (lane >> 2);
    const int ncol = n0 + wn*64 + 2*(lane & 3);
    const bool vec_ok = ((N & 1) == 0);
    #pragma unroll
    for (int mi = 0; mi < 2; mi++) {
        #pragma unroll
        for (int nj = 0; nj < 8; nj++) {
            int c = ncol + nj*8;
            #pragma unroll
            for (int h2 = 0; h2 < 2; h2++) {
                int rr = mrow + mi*16 + h2*8;
                float v0 = acc[mi][nj][h2*2], v1 = acc[mi][nj][h2*2+1];
                if (EPI >= 1 && c < N)     v0 += bias[c];
                if (EPI >= 1 && c+1 < N)   v1 += bias[c+1];
                if (EPI == 2) { v0 = gelu_f(v0); v1 = gelu_f(v1); }
                if (OUT == 2) {
                    int which = c / E_, e = c % E_;
                    int hh = e >> 6, d = e & 63;
                    int b = rr >> 10, t = rr & (T_-1);
                    if (which == 0) { v0 *= 0.125f; v1 *= 0.125f; }  // pre-scale q
                    size_t off = (((size_t)(b*H_ + hh)*T_) + t)*D_ + d;
                    __nv_bfloat16 h0, l0, h1, l1;
                    split_bf(v0, h0, l0); split_bf(v1, h1, l1);
                    __nv_bfloat162 hv; hv.x = h0; hv.y = h1;
                    __nv_bfloat162 lv; lv.x = l0; lv.y = l1;
                    *(__nv_bfloat162*)(Ch + (size_t)(2*which)*BHTD_ + off)   = hv;
                    *(__nv_bfloat162*)(Ch + (size_t)(2*which+1)*BHTD_ + off) = lv;
                } else if (OUT == 1) {
                    if (EPI == 3) {
                        v0 += res[(size_t)rr*N + c]; v1 += res[(size_t)rr*N + c + 1];
                    }
                    __nv_bfloat16 h0, l0, h1, l1;
                    split_bf(v0, h0, l0); split_bf(v1, h1, l1);
                    __nv_bfloat162 hv; hv.x = h0; hv.y = h1;
                    __nv_bfloat162 lv; lv.x = l0; lv.y = l1;
                    *(__nv_bfloat162*)(Ch + (size_t)rr*N + c) = hv;
                    *(__nv_bfloat162*)(Cl + (size_t)rr*N + c) = lv;
                } else {
                    if (vec_ok && c + 1 < N) {
                        if (EPI == 3) {
                            v0 += res[(size_t)rr*N + c]; v1 += res[(size_t)rr*N + c + 1];
                        }
                        float2 o; o.x = v0; o.y = v1;
                        *(float2*)(C + (size_t)rr*N + c) = o;
                    } else {
                        if (c < N) {
                            if (EPI == 3) v0 += res[(size_t)rr*N + c];
                            C[(size_t)rr*N + c] = v0;
                        }
                        if (c + 1 < N) {
                            if (EPI == 3) v1 += res[(size_t)rr*N + c + 1];
                            C[(size_t)rr*N + c + 1] = v1;
                        }
                    }
                }
            }
        }
    }
}

// ---------------- tensor-core flash attention -------------------------------
// CTA: 128 q rows (8 warps x 16 rows, each warp covers full 64-wide k tile).
// S = QhKh + QlKh + QhKl (fp32 acc); P split hi/lo in-register; O += PhVh+PlVh+PhVl.
#define FROW 144                 // smem row stride bytes (64 bf16 + pad)
#define FA2_SMEM 36864           // Kh|Kl|Vh|Vl (also Qh|Ql staging)

__global__ void __launch_bounds__(256)
flash2_k(const __nv_bfloat16* __restrict__ qkv6,
         __nv_bfloat16* __restrict__ yh, __nv_bfloat16* __restrict__ yl) {
    extern __shared__ char fsm[];
    const uint32_t sb = cvta_smem(fsm);
    const int tid = threadIdx.x, lane = tid & 31, w = tid >> 5;
    const int q0 = blockIdx.x * 128, bh = blockIdx.y;
    const __nv_bfloat16 *qh_g = qkv6,            *ql_g = qkv6 + BHTD_;
    const __nv_bfloat16 *kh_g = qkv6 + 2*BHTD_,  *kl_g = qkv6 + 3*BHTD_;
    const __nv_bfloat16 *vh_g = qkv6 + 4*BHTD_,  *vl_g = qkv6 + 5*BHTD_;
    const size_t hb = (size_t)bh * T_ * D_;

    // ---- stage Q (128 x 64) hi/lo into smem, pull A-frags to registers ----
    #pragma unroll
    for (int i = 0; i < 8; i++) {
        int j = tid + i*256;               // 0..2047
        int arr = j >> 10;                 // 0 hi, 1 lo
        int row = (j >> 3) & 127, ch = j & 7;
        const __nv_bfloat16* src = (arr ? ql_g : qh_g) + hb + (size_t)(q0+row)*D_ + ch*8;
        cpa16(sb + (uint32_t)arr*18432u + (uint32_t)(row*FROW + ch*16), src);
    }
    asm volatile("cp.async.commit_group;" ::: "memory");
    asm volatile("cp.async.wait_group 0;" ::: "memory");
    __syncthreads();

    uint32_t qah[4][4], qal[4][4];
    {
        uint32_t base = sb + (uint32_t)((w*16 + (lane&15))*FROW) + (uint32_t)((lane>>4)*16);
        #pragma unroll
        for (int kc = 0; kc < 4; kc++) {
            ldsm4(qah[kc], base + kc*32);
            ldsm4(qal[kc], base + 18432u + kc*32);
        }
    }
    __syncthreads();

    const uint32_t Kh = sb, Kl = sb + 9216u, Vh = sb + 18432u, Vl = sb + 27648u;
    float m0 = -1e30f, m1 = -1e30f, l0 = 0.f, l1 = 0.f;
    float acc[8][4];
    #pragma unroll
    for (int nj = 0; nj < 8; nj++)
        #pragma unroll
        for (int t = 0; t < 4; t++) acc[nj][t] = 0.f;

    const int my_qmax = q0 + w*16 + 15;
    const int nkt = (q0 + 128) >> 6;
    for (int kt = 0; kt < nkt; kt++) {
        __syncthreads();
        #pragma unroll
        for (int i = 0; i < 8; i++) {
            int j = tid + i*256;
            int arr = j >> 9;              // 0 kh, 1 kl, 2 vh, 3 vl
            int row = (j >> 3) & 63, ch = j & 7;
            const __nv_bfloat16* src =
                (arr==0 ? kh_g : arr==1 ? kl_g : arr==2 ? vh_g : vl_g)
                + hb + (size_t)(kt*64+row)*D_ + ch*8;
            cpa16(sb + (uint32_t)arr*9216u + (uint32_t)(row*FROW + ch*16), src);
        }
        asm volatile("cp.async.commit_group;" ::: "memory");
        asm volatile("cp.async.wait_group 0;" ::: "memory");
        __syncthreads();
        if (kt*64 > my_qmax) continue;

        // ---- S = Q K^T (3-term), fp32 frags f[8][4] ----
        float f[8][4];
        #pragma unroll
        for (int nj = 0; nj < 8; nj++)
            #pragma unroll
            for (int t = 0; t < 4; t++) f[nj][t] = 0.f;
        #pragma unroll
        for (int kc = 0; kc < 4; kc++) {
            uint32_t koff = (uint32_t)(((lane&7) + ((lane>>4)<<3))*FROW)
                          + (uint32_t)(kc*32 + (((lane>>3)&1)<<4));
            #pragma unroll
            for (int ng = 0; ng < 4; ng++) {
                uint32_t th[4], tl[4];
                ldsm4(th, Kh + (uint32_t)(ng*16*FROW) + koff);
                ldsm4(tl, Kl + (uint32_t)(ng*16*FROW) + koff);
                mma16816(f[2*ng],   qah[kc], th);
                mma16816(f[2*ng],   qal[kc], th);
                mma16816(f[2*ng],   qah[kc], tl);
                mma16816(f[2*ng+1], qah[kc], th+2);
                mma16816(f[2*ng+1], qal[kc], th+2);
                mma16816(f[2*ng+1], qah[kc], tl+2);
            }
        }
        // ---- causal mask (boundary tiles only) ----
        if (kt*64 + 63 > q0 + w*16) {
            int qg0 = q0 + w*16 + (lane>>2), qg1 = qg0 + 8;
            #pragma unroll
            for (int nj = 0; nj < 8; nj++) {
                int cc0 = kt*64 + nj*8 + 2*(lane&3), cc1 = cc0 + 1;
                if (cc0 > qg0) f[nj][0] = -1e30f;
                if (cc1 > qg0) f[nj][1] = -1e30f;
                if (cc0 > qg1) f[nj][2] = -1e30f;
                if (cc1 > qg1) f[nj][3] = -1e30f;
            }
        }
        // ---- online softmax (warp-local; 4 lanes share a row) ----
        float mx0 = -1e30f, mx1 = -1e30f;
        #pragma unroll
        for (int nj = 0; nj < 8; nj++) {
            mx0 = fmaxf(mx0, fmaxf(f[nj][0], f[nj][1]));
            mx1 = fmaxf(mx1, fmaxf(f[nj][2], f[nj][3]));
        }
        mx0 = fmaxf(mx0, __shfl_xor_sync(0xffffffffu, mx0, 1));
        mx0 = fmaxf(mx0, __shfl_xor_sync(0xffffffffu, mx0, 2));
        mx1 = fmaxf(mx1, __shfl_xor_sync(0xffffffffu, mx1, 1));
        mx1 = fmaxf(mx1, __shfl_xor_sync(0xffffffffu, mx1, 2));
        float nm0 = fmaxf(m0, mx0), nm1 = fmaxf(m1, mx1);
        float al0 = __expf(m0 - nm0), al1 = __expf(m1 - nm1);
        m0 = nm0; m1 = nm1;

        float s0 = 0.f, s1 = 0.f;
        uint32_t ph[4][4], pl[4][4];       // P A-frags hi/lo per k16 chunk
        #pragma unroll
        for (int kc = 0; kc < 4; kc++) {
            float e0 = __expf(f[2*kc][0]   - nm0), e1 = __expf(f[2*kc][1]   - nm0);
            float e2 = __expf(f[2*kc][2]   - nm1), e3 = __expf(f[2*kc][3]   - nm1);
            float g0 = __expf(f[2*kc+1][0] - nm0), g1 = __expf(f[2*kc+1][1] - nm0);
            float g2 = __expf(f[2*kc+1][2] - nm1), g3 = __expf(f[2*kc+1][3] - nm1);
            s0 += e0 + e1 + g0 + g1;
            s1 += e2 + e3 + g2 + g3;
            ph[kc][0] = packbf(e0, e1);  pl[kc][0] = packbf(e0-bfhi(e0), e1-bfhi(e1));
            ph[kc][1] = packbf(e2, e3);  pl[kc][1] = packbf(e2-bfhi(e2), e3-bfhi(e3));
            ph[kc][2] = packbf(g0, g1);  pl[kc][2] = packbf(g0-bfhi(g0), g1-bfhi(g1));
            ph[kc][3] = packbf(g2, g3);  pl[kc][3] = packbf(g2-bfhi(g2), g3-bfhi(g3));
        }
        s0 += __shfl_xor_sync(0xffffffffu, s0, 1);
        s0 += __shfl_xor_sync(0xffffffffu, s0, 2);
        s1 += __shfl_xor_sync(0xffffffffu, s1, 1);
        s1 += __shfl_xor_sync(0xffffffffu, s1, 2);
        l0 = l0 * al0 + s0;
        l1 = l1 * al1 + s1;
        #pragma unroll
        for (int nj = 0; nj < 8; nj++) {
            acc[nj][0] *= al0; acc[nj][1] *= al0;
            acc[nj][2] *= al1; acc[nj][3] *= al1;
        }
        // ---- O += P V (3-term), V via ldmatrix.trans ----
        #pragma unroll
        for (int kc = 0; kc < 4; kc++) {
            uint32_t voff = (uint32_t)((kc*16 + (lane&7) + (((lane>>3)&1)<<3))*FROW)
                          + (uint32_t)((lane>>4)*16);
            #pragma unroll
            for (int ng = 0; ng < 4; ng++) {
                uint32_t th[4], tl[4];
                ldsm4t(th, Vh + voff + (uint32_t)(ng*32));
                ldsm4t(tl, Vl + voff + (uint32_t)(ng*32));
                mma16816(acc[2*ng],   ph[kc], th);
                mma16816(acc[2*ng],   pl[kc], th);
                mma16816(acc[2*ng],   ph[kc], tl);
                mma16816(acc[2*ng+1], ph[kc], th+2);
                mma16816(acc[2*ng+1], pl[kc], th+2);
                mma16816(acc[2*ng+1], ph[kc], tl+2);
            }
        }
    }

    // ---- output ----
    const float inv0 = 1.f / l0, inv1 = 1.f / l1;
    const int b = bh / H_, h = bh % H_;
    const int r0g = q0 + w*16 + (lane >> 2);
    const size_t base0 = (size_t)(b*T_ + r0g)*E_ + h*64 + 2*(lane & 3);
    const size_t base1 = base0 + (size_t)8*E_;
    #pragma unroll
    for (int nj = 0; nj < 8; nj++) {
        float o0 = acc[nj][0]*inv0, o1 = acc[nj][1]*inv0;
        float o2 = acc[nj][2]*inv1, o3 = acc[nj][3]*inv1;
        __nv_bfloat16 h0,lo0,h1,lo1,h2,lo2,h3,lo3;
        split_bf(o0,h0,lo0); split_bf(o1,h1,lo1);
        split_bf(o2,h2,lo2); split_bf(o3,h3,lo3);
        __nv_bfloat162 a; a.x=h0; a.y=h1;
        __nv_bfloat162 c; c.x=lo0; c.y=lo1;
        __nv_bfloat162 d2; d2.x=h2; d2.y=h3;
        __nv_bfloat162 e2; e2.x=lo2; e2.y=lo3;
        *(__nv_bfloat162*)(yh + base0 + nj*8) = a;
        *(__nv_bfloat162*)(yl + base0 + nj*8) = c;
        *(__nv_bfloat162*)(yh + base1 + nj*8) = d2;
        *(__nv_bfloat162*)(yl + base1 + nj*8) = e2;
    }
}

// ---------------- weight transpose+split: W[K,N] fp32 -> WT hi/lo [N,K] bf16 -
__global__ void transpose_split_k(const float* __restrict__ W,
                                  __nv_bfloat16* __restrict__ WTh,
                                  __nv_bfloat16* __restrict__ WTl,
                                  int K, int N) {
    __shared__ float t[32][33];
    const size_t lstride = (size_t)K * N;
    const float* Wl = W + lstride * blockIdx.z;
    __nv_bfloat16* Hh = WTh + lstride * blockIdx.z;
    __nv_bfloat16* Hl = WTl + lstride * blockIdx.z;
    int n0 = blockIdx.x * 32, k0 = blockIdx.y * 32;
    int x = threadIdx.x, y = threadIdx.y;
    #pragma unroll
    for (int i = 0; i < 32; i += 8)
        t[y + i][x] = Wl[(size_t)(k0 + y + i) * N + n0 + x];
    __syncthreads();
    #pragma unroll
    for (int i = 0; i < 32; i += 8) {
        float v = t[x][y + i];
        __nv_bfloat16 h, l; split_bf(v, h, l);
        Hh[(size_t)(n0 + y + i) * K + k0 + x] = h;
        Hl[(size_t)(n0 + y + i) * K + k0 + x] = l;
    }
}

// ---------------- wte pad+split ----------------
__global__ void wte_split_k(const float* __restrict__ wte,
                            __nv_bfloat16* __restrict__ wh,
                            __nv_bfloat16* __restrict__ wl) {
    int i = blockIdx.x * blockDim.x + threadIdx.x;
    if (i >= VP_*E_) return;
    int row = i / E_;
    float v = (row < V_) ? wte[i] : 0.f;
    __nv_bfloat16 h, l; split_bf(v, h, l);
    wh[i] = h; wl[i] = l;
}

// ---------------- embedding ----------------
__global__ void embed_k(const int* __restrict__ idx, const float* __restrict__ wte,
                        const float* __restrict__ wpe, float* __restrict__ x) {
    int i = blockIdx.x * blockDim.x + threadIdx.x;
    if (i >= M_*E_) return;
    int row = i / E_, e = i % E_;
    int t = row & (T_-1);
    x[i] = wte[(size_t)idx[row]*E_ + e] + wpe[t*E_ + e];
}

// ---------------- layernorm -> bf16 hi/lo ----------------
__global__ void ln_k(const float* __restrict__ x, const float* __restrict__ g,
                     const float* __restrict__ b,
                     __nv_bfloat16* __restrict__ oh, __nv_bfloat16* __restrict__ ol) {
    int row = blockIdx.x;
    int tid = threadIdx.x;
    const float* xr = x + (size_t)row*E_;
    __shared__ float s1[256], s2[256];
    float a = 0.f, q = 0.f;
    for (int e = tid; e < E_; e += 256) { float v = xr[e]; a += v; q += v*v; }
    s1[tid] = a; s2[tid] = q; __syncthreads();
    for (int off = 128; off > 0; off >>= 1) {
        if (tid < off) { s1[tid] += s1[tid+off]; s2[tid] += s2[tid+off]; }
        __syncthreads();
    }
    float mu  = s1[0] * (1.f/E_);
    float var = s2[0] * (1.f/E_) - mu*mu;
    float inv = rsqrtf(var + 1e-5f);
    for (int e = tid; e < E_; e += 256) {
        float v = (xr[e] - mu) * inv * g[e] + b[e];
        __nv_bfloat16 h, l; split_bf(v, h, l);
        oh[(size_t)row*E_ + e] = h;
        ol[(size_t)row*E_ + e] = l;
    }
}

// ---------------- launch ----------------
extern "C" void kernel_launch(void* const* d_in, const int* in_sizes, int n_in,
                              void* d_out, int out_size) {
    const int*   idx    = (const int*)  d_in[0];
    const float* wte    = (const float*)d_in[1];
    const float* wpe    = (const float*)d_in[2];
    const float* ln1_g  = (const float*)d_in[3];
    const float* ln1_b  = (const float*)d_in[4];
    const float* attn_w = (const float*)d_in[5];
    const float* attn_b = (const float*)d_in[6];
    const float* proj_w = (const float*)d_in[7];
    const float* proj_b = (const float*)d_in[8];
    const float* ln2_g  = (const float*)d_in[9];
    const float* ln2_b  = (const float*)d_in[10];
    const float* fc_w   = (const float*)d_in[11];
    const float* fc_b   = (const float*)d_in[12];
    const float* fcp_w  = (const float*)d_in[13];
    const float* fcp_b  = (const float*)d_in[14];
    const float* lnf_g  = (const float*)d_in[15];
    const float* lnf_b  = (const float*)d_in[16];
    float* out = (float*)d_out;

    float *x;
    __nv_bfloat16 *qkv6, *xh, *xl, *yh, *yl, *h4h, *h4l;
    __nv_bfloat16 *attnTh, *attnTl, *projTh, *projTl, *fcTh, *fcTl, *fcpTh, *fcpTl;
    __nv_bfloat16 *wteh, *wtel;
    cudaGetSymbolAddress((void**)&x,    g_x);
    cudaGetSymbolAddress((void**)&qkv6, g_qkv6);
    cudaGetSymbolAddress((void**)&xh,   g_xh);   cudaGetSymbolAddress((void**)&xl,  g_xl);
    cudaGetSymbolAddress((void**)&yh,   g_yh);   cudaGetSymbolAddress((void**)&yl,  g_yl);
    cudaGetSymbolAddress((void**)&h4h,  g_h4h);  cudaGetSymbolAddress((void**)&h4l, g_h4l);
    cudaGetSymbolAddress((void**)&attnTh, g_attnTh); cudaGetSymbolAddress((void**)&attnTl, g_attnTl);
    cudaGetSymbolAddress((void**)&projTh, g_projTh); cudaGetSymbolAddress((void**)&projTl, g_projTl);
    cudaGetSymbolAddress((void**)&fcTh,   g_fcTh);   cudaGetSymbolAddress((void**)&fcTl,   g_fcTl);
    cudaGetSymbolAddress((void**)&fcpTh,  g_fcpTh);  cudaGetSymbolAddress((void**)&fcpTl,  g_fcpTl);
    cudaGetSymbolAddress((void**)&wteh,   g_wteh);   cudaGetSymbolAddress((void**)&wtel,   g_wtel);

    cudaFuncSetAttribute(gemm_bf<1,2>, cudaFuncAttributeMaxDynamicSharedMemorySize, GEMM_SMEM);
    cudaFuncSetAttribute(gemm_bf<3,0>, cudaFuncAttributeMaxDynamicSharedMemorySize, GEMM_SMEM);
    cudaFuncSetAttribute(gemm_bf<2,1>, cudaFuncAttributeMaxDynamicSharedMemorySize, GEMM_SMEM);
    cudaFuncSetAttribute(gemm_bf<0,0>, cudaFuncAttributeMaxDynamicSharedMemorySize, GEMM_SMEM);
    cudaFuncSetAttribute(flash2_k,     cudaFuncAttributeMaxDynamicSharedMemorySize, FA2_SMEM);

    dim3 tb(32, 8);
    transpose_split_k<<<dim3(3*E_/32, E_/32, L_), tb>>>(attn_w, attnTh, attnTl, E_, 3*E_);
    transpose_split_k<<<dim3(E_/32,   E_/32, L_), tb>>>(proj_w, projTh, projTl, E_, E_);
    transpose_split_k<<<dim3(4*E_/32, E_/32, L_), tb>>>(fc_w,   fcTh,   fcTl,   E_, 4*E_);
    transpose_split_k<<<dim3(E_/32, 4*E_/32, L_), tb>>>(fcp_w,  fcpTh,  fcpTl,  4*E_, E_);
    wte_split_k<<<(VP_*E_ + 255)/256, 256>>>(wte, wteh, wtel);

    embed_k<<<(M_*E_ + 255)/256, 256>>>(idx, wte, wpe, x);

    for (int l = 0; l < L_; l++) {
        ln_k<<<M_, 256>>>(x, ln1_g + l*E_, ln1_b + l*E_, xh, xl);
        gemm_bf<1,2><<<dim3(M_/128, 3*E_/128), 256, GEMM_SMEM>>>(
            xh, xl, attnTh + (size_t)l*3*E_*E_, attnTl + (size_t)l*3*E_*E_,
            attn_b + l*3*E_, nullptr, nullptr, qkv6, nullptr, M_, 3*E_, E_);
        flash2_k<<<dim3(T_/128, B_*H_), 256, FA2_SMEM>>>(qkv6, yh, yl);
        gemm_bf<3,0><<<dim3(M_/128, E_/128), 256, GEMM_SMEM>>>(
            yh, yl, projTh + (size_t)l*E_*E_, projTl + (size_t)l*E_*E_,
            proj_b + l*E_, x, x, nullptr, nullptr, M_, E_, E_);
        ln_k<<<M_, 256>>>(x, ln2_g + l*E_, ln2_b + l*E_, xh, xl);
        gemm_bf<2,1><<<dim3(M_/128, 4*E_/128), 256, GEMM_SMEM>>>(
            xh, xl, fcTh + (size_t)l*4*E_*E_, fcTl + (size_t)l*4*E_*E_,
            fc_b + l*4*E_, nullptr, nullptr, h4h, h4l, M_, 4*E_, E_);
        gemm_bf<3,0><<<dim3(M_/128, E_/128), 256, GEMM_SMEM>>>(
            h4h, h4l, fcpTh + (size_t)l*4*E_*E_, fcpTl + (size_t)l*4*E_*E_,
            fcp_b + l*E_, x, x, nullptr, nullptr, M_, E_, 4*E_);
    }

    ln_k<<<M_, 256>>>(x, lnf_g, lnf_b, xh, xl);
    gemm_bf<0,0><<<dim3(M_/128, VP_/128), 256, GEMM_SMEM>>>(
        xh, xl, wteh, wtel, nullptr, nullptr, out, nullptr, nullptr, M_, V_, E_);
}

// round 8
// speedup vs baseline: 3.7509x; 1.0330x over previous
#include <cuda_runtime.h>
#include <cuda_bf16.h>
#include <math.h>
#include <stdint.h>

#define E_ 768
#define L_ 12
#define H_ 12
#define D_ 64
#define B_ 2
#define T_ 1024
#define V_ 50257
#define VP_ 50304
#define M_ (B_*T_)
#define BHTD_ (B_*H_*T_*D_)

// ---------------- scratch ----------------
__device__ float g_x   [M_*E_];
__device__ __nv_bfloat16 g_qkv6[6*BHTD_];    // qh,ql,kh,kl,vh,vl each [B,H,T,D]
__device__ __nv_bfloat16 g_xh [M_*E_],  g_xl [M_*E_];
__device__ __nv_bfloat16 g_yh [M_*E_],  g_yl [M_*E_];
__device__ __nv_bfloat16 g_h4h[M_*4*E_],g_h4l[M_*4*E_];
__device__ __nv_bfloat16 g_attnTh[L_*3*E_*E_], g_attnTl[L_*3*E_*E_];
__device__ __nv_bfloat16 g_projTh[L_*E_*E_],   g_projTl[L_*E_*E_];
__device__ __nv_bfloat16 g_fcTh  [L_*4*E_*E_], g_fcTl  [L_*4*E_*E_];
__device__ __nv_bfloat16 g_fcpTh [L_*4*E_*E_], g_fcpTl [L_*4*E_*E_];
__device__ __nv_bfloat16 g_wteh  [VP_*E_],     g_wtel  [VP_*E_];

// ---------------- helpers ----------------
__device__ __forceinline__ uint32_t cvta_smem(const void* p){
    uint32_t a;
    asm("{.reg .u64 t; cvta.to.shared.u64 t, %1; cvt.u32.u64 %0, t;}" : "=r"(a) : "l"(p));
    return a;
}
__device__ __forceinline__ void ldsm4(uint32_t* r, uint32_t addr){
    asm volatile("ldmatrix.sync.aligned.m8n8.x4.shared.b16 {%0,%1,%2,%3}, [%4];"
        : "=r"(r[0]),"=r"(r[1]),"=r"(r[2]),"=r"(r[3]) : "r"(addr));
}
__device__ __forceinline__ void ldsm4t(uint32_t* r, uint32_t addr){
    asm volatile("ldmatrix.sync.aligned.m8n8.x4.trans.shared.b16 {%0,%1,%2,%3}, [%4];"
        : "=r"(r[0]),"=r"(r[1]),"=r"(r[2]),"=r"(r[3]) : "r"(addr));
}
__device__ __forceinline__ void mma16816(float* d, const uint32_t* a, const uint32_t* b){
    asm volatile("mma.sync.aligned.m16n8k16.row.col.f32.bf16.bf16.f32 "
        "{%0,%1,%2,%3}, {%4,%5,%6,%7}, {%8,%9}, {%0,%1,%2,%3};"
        : "+f"(d[0]),"+f"(d[1]),"+f"(d[2]),"+f"(d[3])
        : "r"(a[0]),"r"(a[1]),"r"(a[2]),"r"(a[3]), "r"(b[0]),"r"(b[1]));
}
__device__ __forceinline__ void cpa16(uint32_t s, const void* g){
    asm volatile("cp.async.cg.shared.global [%0], [%1], 16;" :: "r"(s), "l"(g));
}
__device__ __forceinline__ float gelu_f(float v){
    return 0.5f * v * (1.0f + erff(v * 0.70710678118654752f));
}
__device__ __forceinline__ uint32_t packbf(float a, float b){
    __nv_bfloat162 t = __floats2bfloat162_rn(a, b);
    return *reinterpret_cast<uint32_t*>(&t);
}
__device__ __forceinline__ float bfhi(float a){
    return __bfloat162float(__float2bfloat16_rn(a));
}
__device__ __forceinline__ void split_bf(float v, __nv_bfloat16& h, __nv_bfloat16& l){
    h = __float2bfloat16_rn(v);
    l = __float2bfloat16_rn(v - __bfloat162float(h));
}

// ------- bf16-split mma.sync GEMM: 128x128x32, 3-stage single-sync ring ------
// row layout (144B): [32 bf16 hi | 32 bf16 lo | 16B pad]; A at 0, B at +18432
#define GROWB 144
#define GOPB  18432              // per-operand buffer bytes (128*144)
#define GSTAGE 36864             // A+B per stage
#define GEMM_SMEM (3*GSTAGE)     // 110592 -> 2 CTAs/SM

// EPI: 0 none, 1 +bias, 2 gelu(+bias), 3 +bias+residual
// OUT: 0 fp32 C, 1 bf16 hi/lo (Ch,Cl), 2 qkv hi/lo head-scatter into Ch
template<int EPI, int OUT>
__global__ void __launch_bounds__(256, 2)
gemm_bf(const __nv_bfloat16* __restrict__ Ahg, const __nv_bfloat16* __restrict__ Alg,
        const __nv_bfloat16* __restrict__ Bhg, const __nv_bfloat16* __restrict__ Blg,
        const float* __restrict__ bias, const float* __restrict__ res,
        float* __restrict__ C, __nv_bfloat16* __restrict__ Ch,
        __nv_bfloat16* __restrict__ Cl, int M, int N, int K) {
    extern __shared__ char smraw[];
    const uint32_t sb = cvta_smem(smraw);
    const int tid = threadIdx.x;
    const int lane = tid & 31, wid = tid >> 5;
    const int wm = wid & 3, wn = wid >> 2;
    const int m0 = blockIdx.x * 128, n0 = blockIdx.y * 128;
    const int nkb = K >> 5;

    float acc[2][8][4];
    #pragma unroll
    for (int i = 0; i < 2; i++)
        #pragma unroll
        for (int j = 0; j < 8; j++)
            #pragma unroll
            for (int t = 0; t < 4; t++) acc[i][j][t] = 0.f;

    // loader: 2048 16B chunks per stage / 256 threads = 8 per thread
    // j = tid + i*256: op = j>>10, row = (j>>3)&127, ch = j&7 (0-3 hi, 4-7 lo)
    auto load_stage = [&](int kb){
        const uint32_t st = sb + (uint32_t)(kb % 3) * GSTAGE;
        const int k0 = kb * 32;
        #pragma unroll
        for (int i = 0; i < 8; i++) {
            int j = tid + (i << 8);
            int op = j >> 10, row = (j >> 3) & 127, ch = j & 7;
            const __nv_bfloat16* src =
                (op ? (ch < 4 ? Bhg : Blg) : (ch < 4 ? Ahg : Alg))
                + (size_t)((op ? n0 : m0) + row) * K + k0 + (ch & 3) * 8;
            cpa16(st + (uint32_t)(op*GOPB + row*GROWB + ch*16), src);
        }
    };

    load_stage(0);
    asm volatile("cp.async.commit_group;" ::: "memory");
    load_stage(1);
    asm volatile("cp.async.commit_group;" ::: "memory");

    for (int kb = 0; kb < nkb; kb++) {
        asm volatile("cp.async.wait_group 1;" ::: "memory");
        __syncthreads();
        // all warps finished compute(kb-1) -> stage (kb-1)%3 == (kb+2)%3 free
        if (kb + 2 < nkb) load_stage(kb + 2);
        asm volatile("cp.async.commit_group;" ::: "memory");

        const uint32_t st = sb + (uint32_t)(kb % 3) * GSTAGE;
        const uint32_t Ab = st, Bb = st + GOPB;
        #pragma unroll
        for (int ks = 0; ks < 2; ks++) {
            uint32_t ah[2][4], al[2][4], bhf[8][2], blf[8][2];
            #pragma unroll
            for (int mi = 0; mi < 2; mi++) {
                int row = wm*32 + mi*16 + (lane & 15);
                int ch  = 2*ks + (lane >> 4);
                uint32_t off = (uint32_t)(row*GROWB + ch*16);
                ldsm4(ah[mi], Ab + off);
                ldsm4(al[mi], Ab + off + 64);
            }
            #pragma unroll
            for (int p2 = 0; p2 < 4; p2++) {
                int nr = wn*64 + p2*16 + (lane & 7) + ((lane >> 4) << 3);
                int ch = 2*ks + ((lane >> 3) & 1);
                uint32_t off = (uint32_t)(nr*GROWB + ch*16);
                uint32_t t[4];
                ldsm4(t, Bb + off);
                bhf[2*p2][0]=t[0]; bhf[2*p2][1]=t[1]; bhf[2*p2+1][0]=t[2]; bhf[2*p2+1][1]=t[3];
                ldsm4(t, Bb + off + 64);
                blf[2*p2][0]=t[0]; blf[2*p2][1]=t[1]; blf[2*p2+1][0]=t[2]; blf[2*p2+1][1]=t[3];
            }
            #pragma unroll
            for (int mi = 0; mi < 2; mi++)
                #pragma unroll
                for (int nj = 0; nj < 8; nj++) {
                    mma16816(acc[mi][nj], ah[mi], bhf[nj]);
                    mma16816(acc[mi][nj], ah[mi], blf[nj]);
                    mma16816(acc[mi][nj], al[mi], bhf[nj]);
                }
        }
    }

    // ---- epilogue ----
    const int mrow = m0 + wm*32 + (lane >> 2);
    const int ncol = n0 + wn*64 + 2*(lane & 3);
    const bool vec_ok = ((N & 1) == 0);
    #pragma unroll
    for (int mi = 0; mi < 2; mi++) {
        #pragma unroll
        for (int nj = 0; nj < 8; nj++) {
            int c = ncol + nj*8;
            #pragma unroll
            for (int h2 = 0; h2 < 2; h2++) {
                int rr = mrow + mi*16 + h2*8;
                float v0 = acc[mi][nj][h2*2], v1 = acc[mi][nj][h2*2+1];
                if (EPI >= 1 && c < N)     v0 += bias[c];
                if (EPI >= 1 && c+1 < N)   v1 += bias[c+1];
                if (EPI == 2) { v0 = gelu_f(v0); v1 = gelu_f(v1); }
                if (OUT == 2) {
                    int which = c / E_, e = c % E_;
                    int hh = e >> 6, d = e & 63;
                    int b = rr >> 10, t = rr & (T_-1);
                    if (which == 0) { v0 *= 0.125f; v1 *= 0.125f; }
                    size_t off = (((size_t)(b*H_ + hh)*T_) + t)*D_ + d;
                    __nv_bfloat16 h0, l0, h1, l1;
                    split_bf(v0, h0, l0); split_bf(v1, h1, l1);
                    __nv_bfloat162 hv; hv.x = h0; hv.y = h1;
                    __nv_bfloat162 lv; lv.x = l0; lv.y = l1;
                    *(__nv_bfloat162*)(Ch + (size_t)(2*which)*BHTD_ + off)   = hv;
                    *(__nv_bfloat162*)(Ch + (size_t)(2*which+1)*BHTD_ + off) = lv;
                } else if (OUT == 1) {
                    if (EPI == 3) {
                        v0 += res[(size_t)rr*N + c]; v1 += res[(size_t)rr*N + c + 1];
                    }
                    __nv_bfloat16 h0, l0, h1, l1;
                    split_bf(v0, h0, l0); split_bf(v1, h1, l1);
                    __nv_bfloat162 hv; hv.x = h0; hv.y = h1;
                    __nv_bfloat162 lv; lv.x = l0; lv.y = l1;
                    *(__nv_bfloat162*)(Ch + (size_t)rr*N + c) = hv;
                    *(__nv_bfloat162*)(Cl + (size_t)rr*N + c) = lv;
                } else {
                    if (vec_ok && c + 1 < N) {
                        if (EPI == 3) {
                            v0 += res[(size_t)rr*N + c]; v1 += res[(size_t)rr*N + c + 1];
                        }
                        float2 o; o.x = v0; o.y = v1;
                        *(float2*)(C + (size_t)rr*N + c) = o;
                    } else {
                        if (c < N) {
                            if (EPI == 3) v0 += res[(size_t)rr*N + c];
                            C[(size_t)rr*N + c] = v0;
                        }
                        if (c + 1 < N) {
                            if (EPI == 3) v1 += res[(size_t)rr*N + c + 1];
                            C[(size_t)rr*N + c + 1] = v1;
                        }
                    }
                }
            }
        }
    }
}

// ---------------- tensor-core flash attention (unchanged) -------------------
#define FROW 144
#define FA2_SMEM 36864

__global__ void __launch_bounds__(256)
flash2_k(const __nv_bfloat16* __restrict__ qkv6,
         __nv_bfloat16* __restrict__ yh, __nv_bfloat16* __restrict__ yl) {
    extern __shared__ char fsm[];
    const uint32_t sb = cvta_smem(fsm);
    const int tid = threadIdx.x, lane = tid & 31, w = tid >> 5;
    const int q0 = blockIdx.x * 128, bh = blockIdx.y;
    const __nv_bfloat16 *qh_g = qkv6,            *ql_g = qkv6 + BHTD_;
    const __nv_bfloat16 *kh_g = qkv6 + 2*BHTD_,  *kl_g = qkv6 + 3*BHTD_;
    const __nv_bfloat16 *vh_g = qkv6 + 4*BHTD_,  *vl_g = qkv6 + 5*BHTD_;
    const size_t hb = (size_t)bh * T_ * D_;

    #pragma unroll
    for (int i = 0; i < 8; i++) {
        int j = tid + i*256;
        int arr = j >> 10;
        int row = (j >> 3) & 127, ch = j & 7;
        const __nv_bfloat16* src = (arr ? ql_g : qh_g) + hb + (size_t)(q0+row)*D_ + ch*8;
        cpa16(sb + (uint32_t)arr*18432u + (uint32_t)(row*FROW + ch*16), src);
    }
    asm volatile("cp.async.commit_group;" ::: "memory");
    asm volatile("cp.async.wait_group 0;" ::: "memory");
    __syncthreads();

    uint32_t qah[4][4], qal[4][4];
    {
        uint32_t base = sb + (uint32_t)((w*16 + (lane&15))*FROW) + (uint32_t)((lane>>4)*16);
        #pragma unroll
        for (int kc = 0; kc < 4; kc++) {
            ldsm4(qah[kc], base + kc*32);
            ldsm4(qal[kc], base + 18432u + kc*32);
        }
    }
    __syncthreads();

    const uint32_t Kh = sb, Kl = sb + 9216u, Vh = sb + 18432u, Vl = sb + 27648u;
    float m0 = -1e30f, m1 = -1e30f, l0 = 0.f, l1 = 0.f;
    float acc[8][4];
    #pragma unroll
    for (int nj = 0; nj < 8; nj++)
        #pragma unroll
        for (int t = 0; t < 4; t++) acc[nj][t] = 0.f;

    const int my_qmax = q0 + w*16 + 15;
    const int nkt = (q0 + 128) >> 6;
    for (int kt = 0; kt < nkt; kt++) {
        __syncthreads();
        #pragma unroll
        for (int i = 0; i < 8; i++) {
            int j = tid + i*256;
            int arr = j >> 9;
            int row = (j >> 3) & 63, ch = j & 7;
            const __nv_bfloat16* src =
                (arr==0 ? kh_g : arr==1 ? kl_g : arr==2 ? vh_g : vl_g)
                + hb + (size_t)(kt*64+row)*D_ + ch*8;
            cpa16(sb + (uint32_t)arr*9216u + (uint32_t)(row*FROW + ch*16), src);
        }
        asm volatile("cp.async.commit_group;" ::: "memory");
        asm volatile("cp.async.wait_group 0;" ::: "memory");
        __syncthreads();
        if (kt*64 > my_qmax) continue;

        float f[8][4];
        #pragma unroll
        for (int nj = 0; nj < 8; nj++)
            #pragma unroll
            for (int t = 0; t < 4; t++) f[nj][t] = 0.f;
        #pragma unroll
        for (int kc = 0; kc < 4; kc++) {
            uint32_t koff = (uint32_t)(((lane&7) + ((lane>>4)<<3))*FROW)
                          + (uint32_t)(kc*32 + (((lane>>3)&1)<<4));
            #pragma unroll
            for (int ng = 0; ng < 4; ng++) {
                uint32_t th[4], tl[4];
                ldsm4(th, Kh + (uint32_t)(ng*16*FROW) + koff);
                ldsm4(tl, Kl + (uint32_t)(ng*16*FROW) + koff);
                mma16816(f[2*ng],   qah[kc], th);
                mma16816(f[2*ng],   qal[kc], th);
                mma16816(f[2*ng],   qah[kc], tl);
                mma16816(f[2*ng+1], qah[kc], th+2);
                mma16816(f[2*ng+1], qal[kc], th+2);
                mma16816(f[2*ng+1], qah[kc], tl+2);
            }
        }
        if (kt*64 + 63 > q0 + w*16) {
            int qg0 = q0 + w*16 + (lane>>2), qg1 = qg0 + 8;
            #pragma unroll
            for (int nj = 0; nj < 8; nj++) {
                int cc0 = kt*64 + nj*8 + 2*(lane&3), cc1 = cc0 + 1;
                if (cc0 > qg0) f[nj][0] = -1e30f;
                if (cc1 > qg0) f[nj][1] = -1e30f;
                if (cc0 > qg1) f[nj][2] = -1e30f;
                if (cc1 > qg1) f[nj][3] = -1e30f;
            }
        }
        float mx0 = -1e30f, mx1 = -1e30f;
        #pragma unroll
        for (int nj = 0; nj < 8; nj++) {
            mx0 = fmaxf(mx0, fmaxf(f[nj][0], f[nj][1]));
            mx1 = fmaxf(mx1, fmaxf(f[nj][2], f[nj][3]));
        }
        mx0 = fmaxf(mx0, __shfl_xor_sync(0xffffffffu, mx0, 1));
        mx0 = fmaxf(mx0, __shfl_xor_sync(0xffffffffu, mx0, 2));
        mx1 = fmaxf(mx1, __shfl_xor_sync(0xffffffffu, mx1, 1));
        mx1 = fmaxf(mx1, __shfl_xor_sync(0xffffffffu, mx1, 2));
        float nm0 = fmaxf(m0, mx0), nm1 = fmaxf(m1, mx1);
        float al0 = __expf(m0 - nm0), al1 = __expf(m1 - nm1);
        m0 = nm0; m1 = nm1;

        float s0 = 0.f, s1 = 0.f;
        uint32_t ph[4][4], pl[4][4];
        #pragma unroll
        for (int kc = 0; kc < 4; kc++) {
            float e0 = __expf(f[2*kc][0]   - nm0), e1 = __expf(f[2*kc][1]   - nm0);
            float e2 = __expf(f[2*kc][2]   - nm1), e3 = __expf(f[2*kc][3]   - nm1);
            float g0 = __expf(f[2*kc+1][0] - nm0), g1 = __expf(f[2*kc+1][1] - nm0);
            float g2 = __expf(f[2*kc+1][2] - nm1), g3 = __expf(f[2*kc+1][3] - nm1);
            s0 += e0 + e1 + g0 + g1;
            s1 += e2 + e3 + g2 + g3;
            ph[kc][0] = packbf(e0, e1);  pl[kc][0] = packbf(e0-bfhi(e0), e1-bfhi(e1));
            ph[kc][1] = packbf(e2, e3);  pl[kc][1] = packbf(e2-bfhi(e2), e3-bfhi(e3));
            ph[kc][2] = packbf(g0, g1);  pl[kc][2] = packbf(g0-bfhi(g0), g1-bfhi(g1));
            ph[kc][3] = packbf(g2, g3);  pl[kc][3] = packbf(g2-bfhi(g2), g3-bfhi(g3));
        }
        s0 += __shfl_xor_sync(0xffffffffu, s0, 1);
        s0 += __shfl_xor_sync(0xffffffffu, s0, 2);
        s1 += __shfl_xor_sync(0xffffffffu, s1, 1);
        s1 += __shfl_xor_sync(0xffffffffu, s1, 2);
        l0 = l0 * al0 + s0;
        l1 = l1 * al1 + s1;
        #pragma unroll
        for (int nj = 0; nj < 8; nj++) {
            acc[nj][0] *= al0; acc[nj][1] *= al0;
            acc[nj][2] *= al1; acc[nj][3] *= al1;
        }
        #pragma unroll
        for (int kc = 0; kc < 4; kc++) {
            uint32_t voff = (uint32_t)((kc*16 + (lane&7) + (((lane>>3)&1)<<3))*FROW)
                          + (uint32_t)((lane>>4)*16);
            #pragma unroll
            for (int ng = 0; ng < 4; ng++) {
                uint32_t th[4], tl[4];
                ldsm4t(th, Vh + voff + (uint32_t)(ng*32));
                ldsm4t(tl, Vl + voff + (uint32_t)(ng*32));
                mma16816(acc[2*ng],   ph[kc], th);
                mma16816(acc[2*ng],   pl[kc], th);
                mma16816(acc[2*ng],   ph[kc], tl);
                mma16816(acc[2*ng+1], ph[kc], th+2);
                mma16816(acc[2*ng+1], pl[kc], th+2);
                mma16816(acc[2*ng+1], ph[kc], tl+2);
            }
        }
    }

    const float inv0 = 1.f / l0, inv1 = 1.f / l1;
    const int b = bh / H_, h = bh % H_;
    const int r0g = q0 + w*16 + (lane >> 2);
    const size_t base0 = (size_t)(b*T_ + r0g)*E_ + h*64 + 2*(lane & 3);
    const size_t base1 = base0 + (size_t)8*E_;
    #pragma unroll
    for (int nj = 0; nj < 8; nj++) {
        float o0 = acc[nj][0]*inv0, o1 = acc[nj][1]*inv0;
        float o2 = acc[nj][2]*inv1, o3 = acc[nj][3]*inv1;
        __nv_bfloat16 h0,lo0,h1,lo1,h2,lo2,h3,lo3;
        split_bf(o0,h0,lo0); split_bf(o1,h1,lo1);
        split_bf(o2,h2,lo2); split_bf(o3,h3,lo3);
        __nv_bfloat162 a; a.x=h0; a.y=h1;
        __nv_bfloat162 c; c.x=lo0; c.y=lo1;
        __nv_bfloat162 d2; d2.x=h2; d2.y=h3;
        __nv_bfloat162 e2; e2.x=lo2; e2.y=lo3;
        *(__nv_bfloat162*)(yh + base0 + nj*8) = a;
        *(__nv_bfloat162*)(yl + base0 + nj*8) = c;
        *(__nv_bfloat162*)(yh + base1 + nj*8) = d2;
        *(__nv_bfloat162*)(yl + base1 + nj*8) = e2;
    }
}

// ---------------- weight transpose+split ----------------
__global__ void transpose_split_k(const float* __restrict__ W,
                                  __nv_bfloat16* __restrict__ WTh,
                                  __nv_bfloat16* __restrict__ WTl,
                                  int K, int N) {
    __shared__ float t[32][33];
    const size_t lstride = (size_t)K * N;
    const float* Wl = W + lstride * blockIdx.z;
    __nv_bfloat16* Hh = WTh + lstride * blockIdx.z;
    __nv_bfloat16* Hl = WTl + lstride * blockIdx.z;
    int n0 = blockIdx.x * 32, k0 = blockIdx.y * 32;
    int x = threadIdx.x, y = threadIdx.y;
    #pragma unroll
    for (int i = 0; i < 32; i += 8)
        t[y + i][x] = Wl[(size_t)(k0 + y + i) * N + n0 + x];
    __syncthreads();
    #pragma unroll
    for (int i = 0; i < 32; i += 8) {
        float v = t[x][y + i];
        __nv_bfloat16 h, l; split_bf(v, h, l);
        Hh[(size_t)(n0 + y + i) * K + k0 + x] = h;
        Hl[(size_t)(n0 + y + i) * K + k0 + x] = l;
    }
}

// ---------------- wte pad+split ----------------
__global__ void wte_split_k(const float* __restrict__ wte,
                            __nv_bfloat16* __restrict__ wh,
                            __nv_bfloat16* __restrict__ wl) {
    int i = blockIdx.x * blockDim.x + threadIdx.x;
    if (i >= VP_*E_) return;
    int row = i / E_;
    float v = (row < V_) ? wte[i] : 0.f;
    __nv_bfloat16 h, l; split_bf(v, h, l);
    wh[i] = h; wl[i] = l;
}

// ---------------- embedding ----------------
__global__ void embed_k(const int* __restrict__ idx, const float* __restrict__ wte,
                        const float* __restrict__ wpe, float* __restrict__ x) {
    int i = blockIdx.x * blockDim.x + threadIdx.x;
    if (i >= M_*E_) return;
    int row = i / E_, e = i % E_;
    int t = row & (T_-1);
    x[i] = wte[(size_t)idx[row]*E_ + e] + wpe[t*E_ + e];
}

// ---------------- layernorm: 1 warp / row, shfl reduce ----------------
__global__ void __launch_bounds__(256)
ln_k(const float* __restrict__ x, const float* __restrict__ g,
     const float* __restrict__ b,
     __nv_bfloat16* __restrict__ oh, __nv_bfloat16* __restrict__ ol) {
    const int lane = threadIdx.x & 31;
    const int row = blockIdx.x * 8 + (threadIdx.x >> 5);
    const float* xr = x + (size_t)row*E_;
    float4 v4[6];
    float a = 0.f, q = 0.f;
    #pragma unroll
    for (int i = 0; i < 6; i++) {
        v4[i] = *(const float4*)(xr + (i*32 + lane)*4);
        a += v4[i].x + v4[i].y + v4[i].z + v4[i].w;
        q += v4[i].x*v4[i].x + v4[i].y*v4[i].y + v4[i].z*v4[i].z + v4[i].w*v4[i].w;
    }
    #pragma unroll
    for (int off = 16; off > 0; off >>= 1) {
        a += __shfl_xor_sync(0xffffffffu, a, off);
        q += __shfl_xor_sync(0xffffffffu, q, off);
    }
    float mu  = a * (1.f/E_);
    float var = q * (1.f/E_) - mu*mu;
    float inv = rsqrtf(var + 1e-5f);
    #pragma unroll
    for (int i = 0; i < 6; i++) {
        int e = (i*32 + lane)*4;
        float o0 = (v4[i].x - mu)*inv*g[e+0] + b[e+0];
        float o1 = (v4[i].y - mu)*inv*g[e+1] + b[e+1];
        float o2 = (v4[i].z - mu)*inv*g[e+2] + b[e+2];
        float o3 = (v4[i].w - mu)*inv*g[e+3] + b[e+3];
        __nv_bfloat16 h0,l0,h1,l1,h2,l2,h3,l3;
        split_bf(o0,h0,l0); split_bf(o1,h1,l1);
        split_bf(o2,h2,l2); split_bf(o3,h3,l3);
        __nv_bfloat162 hv0; hv0.x=h0; hv0.y=h1;
        __nv_bfloat162 hv1; hv1.x=h2; hv1.y=h3;
        __nv_bfloat162 lv0; lv0.x=l0; lv0.y=l1;
        __nv_bfloat162 lv1; lv1.x=l2; lv1.y=l3;
        *(__nv_bfloat162*)(oh + (size_t)row*E_ + e)     = hv0;
        *(__nv_bfloat162*)(oh + (size_t)row*E_ + e + 2) = hv1;
        *(__nv_bfloat162*)(ol + (size_t)row*E_ + e)     = lv0;
        *(__nv_bfloat162*)(ol + (size_t)row*E_ + e + 2) = lv1;
    }
}

// ---------------- launch ----------------
extern "C" void kernel_launch(void* const* d_in, const int* in_sizes, int n_in,
                              void* d_out, int out_size) {
    const int*   idx    = (const int*)  d_in[0];
    const float* wte    = (const float*)d_in[1];
    const float* wpe    = (const float*)d_in[2];
    const float* ln1_g  = (const float*)d_in[3];
    const float* ln1_b  = (const float*)d_in[4];
    const float* attn_w = (const float*)d_in[5];
    const float* attn_b = (const float*)d_in[6];
    const float* proj_w = (const float*)d_in[7];
    const float* proj_b = (const float*)d_in[8];
    const float* ln2_g  = (const float*)d_in[9];
    const float* ln2_b  = (const float*)d_in[10];
    const float* fc_w   = (const float*)d_in[11];
    const float* fc_b   = (const float*)d_in[12];
    const float* fcp_w  = (const float*)d_in[13];
    const float* fcp_b  = (const float*)d_in[14];
    const float* lnf_g  = (const float*)d_in[15];
    const float* lnf_b  = (const float*)d_in[16];
    float* out = (float*)d_out;

    float *x;
    __nv_bfloat16 *qkv6, *xh, *xl, *yh, *yl, *h4h, *h4l;
    __nv_bfloat16 *attnTh, *attnTl, *projTh, *projTl, *fcTh, *fcTl, *fcpTh, *fcpTl;
    __nv_bfloat16 *wteh, *wtel;
    cudaGetSymbolAddress((void**)&x,    g_x);
    cudaGetSymbolAddress((void**)&qkv6, g_qkv6);
    cudaGetSymbolAddress((void**)&xh,   g_xh);   cudaGetSymbolAddress((void**)&xl,  g_xl);
    cudaGetSymbolAddress((void**)&yh,   g_yh);   cudaGetSymbolAddress((void**)&yl,  g_yl);
    cudaGetSymbolAddress((void**)&h4h,  g_h4h);  cudaGetSymbolAddress((void**)&h4l, g_h4l);
    cudaGetSymbolAddress((void**)&attnTh, g_attnTh); cudaGetSymbolAddress((void**)&attnTl, g_attnTl);
    cudaGetSymbolAddress((void**)&projTh, g_projTh); cudaGetSymbolAddress((void**)&projTl, g_projTl);
    cudaGetSymbolAddress((void**)&fcTh,   g_fcTh);   cudaGetSymbolAddress((void**)&fcTl,   g_fcTl);
    cudaGetSymbolAddress((void**)&fcpTh,  g_fcpTh);  cudaGetSymbolAddress((void**)&fcpTl,  g_fcpTl);
    cudaGetSymbolAddress((void**)&wteh,   g_wteh);   cudaGetSymbolAddress((void**)&wtel,   g_wtel);

    cudaFuncSetAttribute(gemm_bf<1,2>, cudaFuncAttributeMaxDynamicSharedMemorySize, GEMM_SMEM);
    cudaFuncSetAttribute(gemm_bf<3,0>, cudaFuncAttributeMaxDynamicSharedMemorySize, GEMM_SMEM);
    cudaFuncSetAttribute(gemm_bf<2,1>, cudaFuncAttributeMaxDynamicSharedMemorySize, GEMM_SMEM);
    cudaFuncSetAttribute(gemm_bf<0,0>, cudaFuncAttributeMaxDynamicSharedMemorySize, GEMM_SMEM);
    cudaFuncSetAttribute(flash2_k,     cudaFuncAttributeMaxDynamicSharedMemorySize, FA2_SMEM);

    dim3 tb(32, 8);
    transpose_split_k<<<dim3(3*E_/32, E_/32, L_), tb>>>(attn_w, attnTh, attnTl, E_, 3*E_);
    transpose_split_k<<<dim3(E_/32,   E_/32, L_), tb>>>(proj_w, projTh, projTl, E_, E_);
    transpose_split_k<<<dim3(4*E_/32, E_/32, L_), tb>>>(fc_w,   fcTh,   fcTl,   E_, 4*E_);
    transpose_split_k<<<dim3(E_/32, 4*E_/32, L_), tb>>>(fcp_w,  fcpTh,  fcpTl,  4*E_, E_);
    wte_split_k<<<(VP_*E_ + 255)/256, 256>>>(wte, wteh, wtel);

    embed_k<<<(M_*E_ + 255)/256, 256>>>(idx, wte, wpe, x);

    for (int l = 0; l < L_; l++) {
        ln_k<<<M_/8, 256>>>(x, ln1_g + l*E_, ln1_b + l*E_, xh, xl);
        gemm_bf<1,2><<<dim3(M_/128, 3*E_/128), 256, GEMM_SMEM>>>(
            xh, xl, attnTh + (size_t)l*3*E_*E_, attnTl + (size_t)l*3*E_*E_,
            attn_b + l*3*E_, nullptr, nullptr, qkv6, nullptr, M_, 3*E_, E_);
        flash2_k<<<dim3(T_/128, B_*H_), 256, FA2_SMEM>>>(qkv6, yh, yl);
        gemm_bf<3,0><<<dim3(M_/128, E_/128), 256, GEMM_SMEM>>>(
            yh, yl, projTh + (size_t)l*E_*E_, projTl + (size_t)l*E_*E_,
            proj_b + l*E_, x, x, nullptr, nullptr, M_, E_, E_);
        ln_k<<<M_/8, 256>>>(x, ln2_g + l*E_, ln2_b + l*E_, xh, xl);
        gemm_bf<2,1><<<dim3(M_/128, 4*E_/128), 256, GEMM_SMEM>>>(
            xh, xl, fcTh + (size_t)l*4*E_*E_, fcTl + (size_t)l*4*E_*E_,
            fc_b + l*4*E_, nullptr, nullptr, h4h, h4l, M_, 4*E_, E_);
        gemm_bf<3,0><<<dim3(M_/128, E_/128), 256, GEMM_SMEM>>>(
            h4h, h4l, fcpTh + (size_t)l*4*E_*E_, fcpTl + (size_t)l*4*E_*E_,
            fcp_b + l*E_, x, x, nullptr, nullptr, M_, E_, 4*E_);
    }

    ln_k<<<M_/8, 256>>>(x, lnf_g, lnf_b, xh, xl);
    gemm_bf<0,0><<<dim3(M_/128, VP_/128), 256, GEMM_SMEM>>>(
        xh, xl, wteh, wtel, nullptr, nullptr, out, nullptr, nullptr, M_, V_, E_);
}